// round 1
// baseline (speedup 1.0000x reference)
#include <cuda_runtime.h>

#define B_  4
#define S_  2048
#define D_  1024
#define H_  16
#define HD_ 64
#define TD_ 3072   // 3*D

// ---------------- scratch (static device globals; no runtime allocation) ----
__device__ float g_q[B_ * H_ * S_ * HD_];      // 33.5 MB
__device__ float g_k[B_ * H_ * S_ * HD_];
__device__ float g_v[B_ * H_ * S_ * HD_];
__device__ float g_vflat[B_ * S_ * D_];        // PV output in [B,H,S,hd] = buggy reshape layout

// ---------------- fast exp: 5 FMA + bit ops, avoids MUFU throughput wall ----
__device__ __forceinline__ float fexp(float x) {
    x = fmaxf(x, -80.0f);                        // inputs are <= 0 (s - m)
    float y = x * 1.44269504088896340736f;       // log2(e)
    float t = y + 12582912.0f;                   // round-to-nearest-int trick (1.5*2^23)
    int   i = __float_as_int(t) - 0x4b400000;    // = rint(y)
    float f = y - (t - 12582912.0f);             // f in [-0.5, 0.5]
    float p =              1.33336500e-3f;
    p = fmaf(p, f,         9.61793571e-3f);
    p = fmaf(p, f,         5.55041086e-2f);
    p = fmaf(p, f,         2.40226507e-1f);
    p = fmaf(p, f,         6.93147181e-1f);
    p = fmaf(p, f,         1.0f);
    return __int_as_float(__float_as_int(p) + (i << 23));
}

// ---------------- SGEMM: C[M,N] = A[M,K] @ W[N,K]^T + bias -------------------
// 128x128 tile, BK=16, 256 threads, 8x8 per-thread microtile.
// EPI=0: store row-major into C.  EPI=1: scatter into g_q/g_k/g_v per QKV layout.
template <int EPI>
__global__ void __launch_bounds__(256)
sgemm_kernel(const float* __restrict__ A, const float* __restrict__ W,
             const float* __restrict__ bias, float* __restrict__ C,
             int M, int N, int K)
{
    const int SA = 132;                      // padded smem stride (floats)
    __shared__ float As[16 * SA];            // [k][m], transposed
    __shared__ float Bs[16 * SA];            // [k][n], transposed

    int tid = threadIdx.x;
    int tx = tid & 15, ty = tid >> 4;
    int m0 = blockIdx.y * 128;
    int n0 = blockIdx.x * 128;

    float acc[8][8];
#pragma unroll
    for (int i = 0; i < 8; i++)
#pragma unroll
        for (int j = 0; j < 8; j++) acc[i][j] = 0.f;

    int lr = tid >> 2;            // 0..63
    int lc = (tid & 3) << 2;      // 0,4,8,12

    for (int k0 = 0; k0 < K; k0 += 16) {
#pragma unroll
        for (int r = 0; r < 2; r++) {
            int row = lr + r * 64;
            float4 av = *(const float4*)(A + (size_t)(m0 + row) * K + k0 + lc);
            As[(lc + 0) * SA + row] = av.x; As[(lc + 1) * SA + row] = av.y;
            As[(lc + 2) * SA + row] = av.z; As[(lc + 3) * SA + row] = av.w;
            float4 bv = *(const float4*)(W + (size_t)(n0 + row) * K + k0 + lc);
            Bs[(lc + 0) * SA + row] = bv.x; Bs[(lc + 1) * SA + row] = bv.y;
            Bs[(lc + 2) * SA + row] = bv.z; Bs[(lc + 3) * SA + row] = bv.w;
        }
        __syncthreads();
#pragma unroll
        for (int k = 0; k < 16; k++) {
            float a[8], b[8];
            *(float4*)&a[0] = *(const float4*)&As[k * SA + ty * 4];
            *(float4*)&a[4] = *(const float4*)&As[k * SA + 64 + ty * 4];
            *(float4*)&b[0] = *(const float4*)&Bs[k * SA + tx * 4];
            *(float4*)&b[4] = *(const float4*)&Bs[k * SA + 64 + tx * 4];
#pragma unroll
            for (int i = 0; i < 8; i++)
#pragma unroll
                for (int j = 0; j < 8; j++)
                    acc[i][j] = fmaf(a[i], b[j], acc[i][j]);
        }
        __syncthreads();
    }

#pragma unroll
    for (int i = 0; i < 8; i++) {
        int m = m0 + ((i < 4) ? (ty * 4 + i) : (64 + ty * 4 + i - 4));
#pragma unroll
        for (int jh = 0; jh < 2; jh++) {
            int n = n0 + jh * 64 + tx * 4;
            float4 v;
            v.x = acc[i][jh * 4 + 0] + bias[n + 0];
            v.y = acc[i][jh * 4 + 1] + bias[n + 1];
            v.z = acc[i][jh * 4 + 2] + bias[n + 2];
            v.w = acc[i][jh * 4 + 3] + bias[n + 3];
            if (EPI == 0) {
                *(float4*)(C + (size_t)m * N + n) = v;
            } else {
                // qkv[b,s,e] -> reshape (b,s,H,3*hd): h=e/192, r=e%192, which=r/64, hd=r%64
                int bb = m >> 11;               // m / S
                int ss = m & (S_ - 1);
                int h  = n / 192;
                int rr = n - h * 192;
                int which = rr >> 6;
                int hd = rr & 63;
                float* dst = (which == 0) ? g_q : (which == 1) ? g_k : g_v;
                *(float4*)(dst + ((size_t)(bb * H_ + h) * S_ + ss) * HD_ + hd) = v;
            }
        }
    }
}

// ---------------- attention: per (b*H+h, q-tile of 64) ----------------------
// Pass 1: online rowmax m / denom l over all keys.
// Pass 2: recompute scores, p = exp(s-m)/l, stream p to gmem, accumulate O = P@V.
static const int ST = 66;   // padded smem stride (floats), even -> float2-aligned

__device__ __forceinline__ void score_tile(const float* Qs, const float* Ks,
                                           int tx, int ty, float s[4][4])
{
#pragma unroll
    for (int i = 0; i < 4; i++)
#pragma unroll
        for (int j = 0; j < 4; j++) s[i][j] = 0.f;
#pragma unroll 8
    for (int d = 0; d < 64; d++) {
        float a[4], b[4];
        *(float2*)&a[0] = *(const float2*)&Qs[d * ST + ty * 4];
        *(float2*)&a[2] = *(const float2*)&Qs[d * ST + ty * 4 + 2];
        *(float2*)&b[0] = *(const float2*)&Ks[d * ST + tx * 4];
        *(float2*)&b[2] = *(const float2*)&Ks[d * ST + tx * 4 + 2];
#pragma unroll
        for (int i = 0; i < 4; i++)
#pragma unroll
            for (int j = 0; j < 4; j++)
                s[i][j] = fmaf(a[i], b[j], s[i][j]);
    }
#pragma unroll
    for (int i = 0; i < 4; i++)
#pragma unroll
        for (int j = 0; j < 4; j++) s[i][j] *= 0.125f;   // 1/sqrt(64)
}

__global__ void __launch_bounds__(256)
attn_kernel(float* __restrict__ gAttn, int writeAttn)
{
    extern __shared__ float sm[];
    float* Qs = sm;                  // [d][i]  64 x ST
    float* Ks = Qs + 64 * ST;        // [d][j]
    float* Vs = Ks + 64 * ST;        // [j][d]
    float* Ps = Vs + 64 * ST;        // [j][i]

    int tid = threadIdx.x;
    int tx = tid & 15, ty = tid >> 4;
    int qt = blockIdx.x;
    int bh = blockIdx.y;
    int sq = qt * 64;

    const float* Qb = g_q + ((size_t)bh * S_ + sq) * HD_;
    const float* Kb = g_k + (size_t)bh * S_ * HD_;
    const float* Vb = g_v + (size_t)bh * S_ * HD_;

    // load Q transposed: Qs[d][i]
    {
        int c4 = tx * 4;
#pragma unroll
        for (int r = 0; r < 4; r++) {
            int i = ty + r * 16;
            float4 v = *(const float4*)(Qb + (size_t)i * HD_ + c4);
            Qs[(c4 + 0) * ST + i] = v.x; Qs[(c4 + 1) * ST + i] = v.y;
            Qs[(c4 + 2) * ST + i] = v.z; Qs[(c4 + 3) * ST + i] = v.w;
        }
    }

    float m4[4], l4[4];
#pragma unroll
    for (int i = 0; i < 4; i++) { m4[i] = -1e30f; l4[i] = 0.f; }

    // ---------------- pass 1: m, l ----------------
    for (int kt = 0; kt < S_ / 64; kt++) {
        __syncthreads();
        {
            int c4 = tx * 4;
#pragma unroll
            for (int r = 0; r < 4; r++) {
                int j = ty + r * 16;
                float4 v = *(const float4*)(Kb + (size_t)(kt * 64 + j) * HD_ + c4);
                Ks[(c4 + 0) * ST + j] = v.x; Ks[(c4 + 1) * ST + j] = v.y;
                Ks[(c4 + 2) * ST + j] = v.z; Ks[(c4 + 3) * ST + j] = v.w;
            }
        }
        __syncthreads();

        float s[4][4];
        score_tile(Qs, Ks, tx, ty, s);

#pragma unroll
        for (int i = 0; i < 4; i++) {
            float tm = fmaxf(fmaxf(s[i][0], s[i][1]), fmaxf(s[i][2], s[i][3]));
#pragma unroll
            for (int o = 8; o > 0; o >>= 1)
                tm = fmaxf(tm, __shfl_xor_sync(0xffffffffu, tm, o));
            float mn = fmaxf(m4[i], tm);
            float ps = fexp(s[i][0] - mn) + fexp(s[i][1] - mn)
                     + fexp(s[i][2] - mn) + fexp(s[i][3] - mn);
#pragma unroll
            for (int o = 8; o > 0; o >>= 1)
                ps += __shfl_xor_sync(0xffffffffu, ps, o);
            l4[i] = l4[i] * fexp(m4[i] - mn) + ps;
            m4[i] = mn;
        }
    }

    float inv[4];
#pragma unroll
    for (int i = 0; i < 4; i++) inv[i] = 1.0f / l4[i];

    float o4[4][4];
#pragma unroll
    for (int i = 0; i < 4; i++)
#pragma unroll
        for (int d = 0; d < 4; d++) o4[i][d] = 0.f;

    // ---------------- pass 2: p, attention out, O = P@V ----------------
    for (int kt = 0; kt < S_ / 64; kt++) {
        __syncthreads();
        {
            int c4 = tx * 4;
#pragma unroll
            for (int r = 0; r < 4; r++) {
                int j = ty + r * 16;
                float4 kv = *(const float4*)(Kb + (size_t)(kt * 64 + j) * HD_ + c4);
                Ks[(c4 + 0) * ST + j] = kv.x; Ks[(c4 + 1) * ST + j] = kv.y;
                Ks[(c4 + 2) * ST + j] = kv.z; Ks[(c4 + 3) * ST + j] = kv.w;
                float4 vv = *(const float4*)(Vb + (size_t)(kt * 64 + j) * HD_ + c4);
                *(float2*)&Vs[j * ST + c4]     = make_float2(vv.x, vv.y);
                *(float2*)&Vs[j * ST + c4 + 2] = make_float2(vv.z, vv.w);
            }
        }
        __syncthreads();

        float s[4][4];
        score_tile(Qs, Ks, tx, ty, s);

#pragma unroll
        for (int i = 0; i < 4; i++) {
            float p0 = fexp(s[i][0] - m4[i]) * inv[i];
            float p1 = fexp(s[i][1] - m4[i]) * inv[i];
            float p2 = fexp(s[i][2] - m4[i]) * inv[i];
            float p3 = fexp(s[i][3] - m4[i]) * inv[i];
            if (writeAttn) {
                *(float4*)(gAttn + ((size_t)bh * S_ + sq + ty * 4 + i) * S_
                                 + kt * 64 + tx * 4) = make_float4(p0, p1, p2, p3);
            }
            Ps[(tx * 4 + 0) * ST + ty * 4 + i] = p0;
            Ps[(tx * 4 + 1) * ST + ty * 4 + i] = p1;
            Ps[(tx * 4 + 2) * ST + ty * 4 + i] = p2;
            Ps[(tx * 4 + 3) * ST + ty * 4 + i] = p3;
        }
        __syncthreads();

#pragma unroll 8
        for (int j = 0; j < 64; j++) {
            float a[4], b[4];
            *(float2*)&a[0] = *(const float2*)&Ps[j * ST + ty * 4];
            *(float2*)&a[2] = *(const float2*)&Ps[j * ST + ty * 4 + 2];
            *(float2*)&b[0] = *(const float2*)&Vs[j * ST + tx * 4];
            *(float2*)&b[2] = *(const float2*)&Vs[j * ST + tx * 4 + 2];
#pragma unroll
            for (int i = 0; i < 4; i++)
#pragma unroll
                for (int d = 0; d < 4; d++)
                    o4[i][d] = fmaf(a[i], b[d], o4[i][d]);
        }
    }

    // write O in [B,H,S,hd] contiguous layout == the reference's buggy reshape
#pragma unroll
    for (int i = 0; i < 4; i++) {
        float4 v = make_float4(o4[i][0], o4[i][1], o4[i][2], o4[i][3]);
        *(float4*)(g_vflat + ((size_t)bh * S_ + sq + ty * 4 + i) * HD_ + tx * 4) = v;
    }
}

// ---------------------------------------------------------------------------
extern "C" void kernel_launch(void* const* d_in, const int* in_sizes, int n_in,
                              void* d_out, int out_size)
{
    const float* x     = (const float*)d_in[0];
    const float* w_qkv = (const float*)d_in[1];
    const float* b_qkv = (const float*)d_in[2];
    const float* w_out = (const float*)d_in[3];
    const float* b_out = (const float*)d_in[4];
    float* out = (float*)d_out;

    const long long BSD  = (long long)B_ * S_ * D_;        // 8,388,608
    const long long BHSS = (long long)B_ * H_ * S_ * S_;   // 268,435,456

    float* outp = nullptr;
    float* attnp = nullptr;
    int wA = 0;
    if ((long long)out_size >= BSD + BHSS) { outp = out; attnp = out + BSD; wA = 1; }
    else if ((long long)out_size == BHSS)  { attnp = out; wA = 1; }
    else                                   { outp = out; }

    // attention kernel needs 67,584 B dynamic smem (> default 48 KB opt-in limit)
    cudaFuncSetAttribute(attn_kernel, cudaFuncAttributeMaxDynamicSharedMemorySize,
                         4 * 64 * ST * (int)sizeof(float));

    // K1: fused QKV projection, scattered into [B,H,S,hd] Q/K/V buffers
    {
        dim3 grid(TD_ / 128, (B_ * S_) / 128);
        sgemm_kernel<1><<<grid, 256>>>(x, w_qkv, b_qkv, nullptr, B_ * S_, TD_, D_);
    }
    // K2: attention (writes normalized attention matrix + PV result)
    {
        dim3 grid(S_ / 64, B_ * H_);
        attn_kernel<<<grid, 256, 4 * 64 * ST * (int)sizeof(float)>>>(attnp, wA);
    }
    // K3: output projection
    if (outp) {
        float* vf = nullptr;
        cudaGetSymbolAddress((void**)&vf, g_vflat);
        dim3 grid(D_ / 128, (B_ * S_) / 128);
        sgemm_kernel<0><<<grid, 256>>>(vf, w_out, b_out, outp, B_ * S_, D_, D_);
    }
}

// round 4
// speedup vs baseline: 1.7997x; 1.7997x over previous
#include <cuda_runtime.h>
#include <cuda_bf16.h>
#include <cstdint>

#define B_  4
#define S_  2048
#define D_  1024
#define H_  16
#define HD_ 64
#define TD_ 3072   // 3*D

// ---------------- scratch (static device globals; no runtime allocation) ----
__device__ float g_q[B_ * H_ * S_ * HD_];
__device__ float g_k[B_ * H_ * S_ * HD_];
__device__ float g_v[B_ * H_ * S_ * HD_];
__device__ float g_vflat[B_ * S_ * D_];   // PV out, [B,H,S,hd] == buggy reshape layout

// ---------------- fast exp (5-FMA poly, avoids MUFU wall) -------------------
__device__ __forceinline__ float fexp(float x) {
    x = fmaxf(x, -80.0f);
    float y = x * 1.44269504088896340736f;
    float t = y + 12582912.0f;
    int   i = __float_as_int(t) - 0x4b400000;
    float f = y - (t - 12582912.0f);
    float p =              1.33336500e-3f;
    p = fmaf(p, f,         9.61793571e-3f);
    p = fmaf(p, f,         5.55041086e-2f);
    p = fmaf(p, f,         2.40226507e-1f);
    p = fmaf(p, f,         6.93147181e-1f);
    p = fmaf(p, f,         1.0f);
    return __int_as_float(__float_as_int(p) + (i << 23));
}

// ---------------- bf16 helpers ----------------------------------------------
__device__ __forceinline__ void split1(float x, __nv_bfloat16& h, __nv_bfloat16& l) {
    h = __float2bfloat16_rn(x);
    l = __float2bfloat16_rn(x - __bfloat162float(h));
}
__device__ __forceinline__ uint32_t pckf(float a, float b) {   // pack 2 floats -> bf16x2
    __nv_bfloat162 t = __halves2bfloat162(__float2bfloat16_rn(a), __float2bfloat16_rn(b));
    return *reinterpret_cast<uint32_t*>(&t);
}
__device__ __forceinline__ uint32_t pckh(__nv_bfloat16 a, __nv_bfloat16 b) {
    __nv_bfloat162 t = __halves2bfloat162(a, b);
    return *reinterpret_cast<uint32_t*>(&t);
}

// HMMA m16n8k16 bf16, fp32 accumulate in-place
__device__ __forceinline__ void mma16816(float c[4], const uint32_t a[4], const uint32_t b[2]) {
    asm volatile(
        "mma.sync.aligned.m16n8k16.row.col.f32.bf16.bf16.f32 "
        "{%0,%1,%2,%3}, {%4,%5,%6,%7}, {%8,%9}, {%0,%1,%2,%3};"
        : "+f"(c[0]), "+f"(c[1]), "+f"(c[2]), "+f"(c[3])
        : "r"(a[0]), "r"(a[1]), "r"(a[2]), "r"(a[3]), "r"(b[0]), "r"(b[1]));
}

// ---------------- smem layout (bf16 elements), stride 72 (pad 64+8) ---------
#define STK 72
#define OFF_QH 0
#define OFF_QL 9216
#define OFF_KH 18432
#define OFF_KL 23040
#define OFF_VTH 27648
#define OFF_VTL 32256
#define SMEM_ELEMS 36864     // 73728 bytes

// ================= attention: HMMA split-bf16, two-pass =====================
// grid (S/128, B*H), 256 threads (8 warps x m16).
__global__ void __launch_bounds__(256)
attn_mma_kernel(float* __restrict__ gAttn, int writeAttn)
{
    extern __shared__ __nv_bfloat16 sm[];
    __nv_bfloat16* Qh  = sm + OFF_QH;
    __nv_bfloat16* Ql  = sm + OFF_QL;
    __nv_bfloat16* Kh  = sm + OFF_KH;
    __nv_bfloat16* Kl  = sm + OFF_KL;
    __nv_bfloat16* Vth = sm + OFF_VTH;
    __nv_bfloat16* Vtl = sm + OFF_VTL;

    const int tid = threadIdx.x;
    const int w = tid >> 5, lane = tid & 31;
    const int gid = lane >> 2, tig = lane & 3;
    const int qt = blockIdx.x, bh = blockIdx.y;
    const int sq = qt * 128;

    const float* Qb = g_q + ((size_t)bh * S_ + sq) * HD_;
    const float* Kb = g_k + (size_t)bh * S_ * HD_;
    const float* Vb = g_v + (size_t)bh * S_ * HD_;

    // ---- load Q tile (128x64), split into hi/lo bf16 -----------------------
#pragma unroll
    for (int it = 0; it < 8; it++) {
        int f4 = it * 256 + tid;
        int r = f4 >> 4, c = (f4 & 15) << 2;
        float4 v = ((const float4*)Qb)[f4];
        __nv_bfloat16 h0,h1,h2,h3,l0,l1,l2,l3;
        split1(v.x,h0,l0); split1(v.y,h1,l1); split1(v.z,h2,l2); split1(v.w,h3,l3);
        *(uint2*)&Qh[r*STK+c] = make_uint2(pckh(h0,h1), pckh(h2,h3));
        *(uint2*)&Ql[r*STK+c] = make_uint2(pckh(l0,l1), pckh(l2,l3));
    }

    const int qr = w*16 + gid;          // this thread's base q-row (and +8)

    float m0=-1e30f, m1=-1e30f, l0s=0.f, l1s=0.f;

    // =================== pass 1: rowmax m, denom l ==========================
    for (int t = 0; t < 32; t++) {
        __syncthreads();
#pragma unroll
        for (int it = 0; it < 4; it++) {
            int f4 = it * 256 + tid;
            int r = f4 >> 4, c = (f4 & 15) << 2;
            float4 v = ((const float4*)(Kb + t * 4096))[f4];
            __nv_bfloat16 h0,h1,h2,h3,lo0,lo1,lo2,lo3;
            split1(v.x,h0,lo0); split1(v.y,h1,lo1); split1(v.z,h2,lo2); split1(v.w,h3,lo3);
            *(uint2*)&Kh[r*STK+c] = make_uint2(pckh(h0,h1), pckh(h2,h3));
            *(uint2*)&Kl[r*STK+c] = make_uint2(pckh(lo0,lo1), pckh(lo2,lo3));
        }
        __syncthreads();

        float s[8][4];
#pragma unroll
        for (int nc = 0; nc < 8; nc++)
            s[nc][0]=s[nc][1]=s[nc][2]=s[nc][3]=0.f;

#pragma unroll
        for (int kc = 0; kc < 4; kc++) {
            int qc = kc*16 + tig*2;
            uint32_t aH[4], aL[4];
            aH[0] = *(const uint32_t*)&Qh[qr*STK + qc];
            aH[1] = *(const uint32_t*)&Qh[(qr+8)*STK + qc];
            aH[2] = *(const uint32_t*)&Qh[qr*STK + qc + 8];
            aH[3] = *(const uint32_t*)&Qh[(qr+8)*STK + qc + 8];
            aL[0] = *(const uint32_t*)&Ql[qr*STK + qc];
            aL[1] = *(const uint32_t*)&Ql[(qr+8)*STK + qc];
            aL[2] = *(const uint32_t*)&Ql[qr*STK + qc + 8];
            aL[3] = *(const uint32_t*)&Ql[(qr+8)*STK + qc + 8];
#pragma unroll
            for (int nc = 0; nc < 8; nc++) {
                int kr = nc*8 + gid;
                uint32_t bH[2], bL[2];
                bH[0] = *(const uint32_t*)&Kh[kr*STK + qc];
                bH[1] = *(const uint32_t*)&Kh[kr*STK + qc + 8];
                bL[0] = *(const uint32_t*)&Kl[kr*STK + qc];
                bL[1] = *(const uint32_t*)&Kl[kr*STK + qc + 8];
                mma16816(s[nc], aH, bH);
                mma16816(s[nc], aH, bL);
                mma16816(s[nc], aL, bH);
            }
        }

        float mx0 = -1e30f, mx1 = -1e30f;
#pragma unroll
        for (int nc = 0; nc < 8; nc++) {
            s[nc][0]*=0.125f; s[nc][1]*=0.125f; s[nc][2]*=0.125f; s[nc][3]*=0.125f;
            mx0 = fmaxf(mx0, fmaxf(s[nc][0], s[nc][1]));
            mx1 = fmaxf(mx1, fmaxf(s[nc][2], s[nc][3]));
        }
        mx0 = fmaxf(mx0, __shfl_xor_sync(0xffffffffu, mx0, 1));
        mx0 = fmaxf(mx0, __shfl_xor_sync(0xffffffffu, mx0, 2));
        mx1 = fmaxf(mx1, __shfl_xor_sync(0xffffffffu, mx1, 1));
        mx1 = fmaxf(mx1, __shfl_xor_sync(0xffffffffu, mx1, 2));
        float mn0 = fmaxf(m0, mx0), mn1 = fmaxf(m1, mx1);
        float ps0 = 0.f, ps1 = 0.f;
#pragma unroll
        for (int nc = 0; nc < 8; nc++) {
            ps0 += fexp(s[nc][0]-mn0) + fexp(s[nc][1]-mn0);
            ps1 += fexp(s[nc][2]-mn1) + fexp(s[nc][3]-mn1);
        }
        ps0 += __shfl_xor_sync(0xffffffffu, ps0, 1);
        ps0 += __shfl_xor_sync(0xffffffffu, ps0, 2);
        ps1 += __shfl_xor_sync(0xffffffffu, ps1, 1);
        ps1 += __shfl_xor_sync(0xffffffffu, ps1, 2);
        l0s = l0s * fexp(m0 - mn0) + ps0;  m0 = mn0;
        l1s = l1s * fexp(m1 - mn1) + ps1;  m1 = mn1;
    }
    const float invl0 = 1.0f / l0s;
    const float invl1 = 1.0f / l1s;

    float o[8][4];
#pragma unroll
    for (int nd = 0; nd < 8; nd++)
        o[nd][0]=o[nd][1]=o[nd][2]=o[nd][3]=0.f;

    // =================== pass 2: normalized P out + O = P@V =================
    for (int t = 0; t < 32; t++) {
        __syncthreads();
#pragma unroll
        for (int it = 0; it < 4; it++) {
            int f4 = it * 256 + tid;
            int r = f4 >> 4, c = (f4 & 15) << 2;
            float4 v = ((const float4*)(Kb + t * 4096))[f4];
            __nv_bfloat16 h0,h1,h2,h3,lo0,lo1,lo2,lo3;
            split1(v.x,h0,lo0); split1(v.y,h1,lo1); split1(v.z,h2,lo2); split1(v.w,h3,lo3);
            *(uint2*)&Kh[r*STK+c] = make_uint2(pckh(h0,h1), pckh(h2,h3));
            *(uint2*)&Kl[r*STK+c] = make_uint2(pckh(lo0,lo1), pckh(lo2,lo3));
            float4 vv = ((const float4*)(Vb + t * 4096))[f4];
            float va[4] = {vv.x, vv.y, vv.z, vv.w};
#pragma unroll
            for (int j = 0; j < 4; j++) {
                __nv_bfloat16 h, lo; split1(va[j], h, lo);
                Vth[(c+j)*STK + r] = h;     // V^T: [d][key]
                Vtl[(c+j)*STK + r] = lo;
            }
        }
        __syncthreads();

        float s[8][4];
#pragma unroll
        for (int nc = 0; nc < 8; nc++)
            s[nc][0]=s[nc][1]=s[nc][2]=s[nc][3]=0.f;

#pragma unroll
        for (int kc = 0; kc < 4; kc++) {
            int qc = kc*16 + tig*2;
            uint32_t aH[4], aL[4];
            aH[0] = *(const uint32_t*)&Qh[qr*STK + qc];
            aH[1] = *(const uint32_t*)&Qh[(qr+8)*STK + qc];
            aH[2] = *(const uint32_t*)&Qh[qr*STK + qc + 8];
            aH[3] = *(const uint32_t*)&Qh[(qr+8)*STK + qc + 8];
            aL[0] = *(const uint32_t*)&Ql[qr*STK + qc];
            aL[1] = *(const uint32_t*)&Ql[(qr+8)*STK + qc];
            aL[2] = *(const uint32_t*)&Ql[qr*STK + qc + 8];
            aL[3] = *(const uint32_t*)&Ql[(qr+8)*STK + qc + 8];
#pragma unroll
            for (int nc = 0; nc < 8; nc++) {
                int kr = nc*8 + gid;
                uint32_t bH[2], bL[2];
                bH[0] = *(const uint32_t*)&Kh[kr*STK + qc];
                bH[1] = *(const uint32_t*)&Kh[kr*STK + qc + 8];
                bL[0] = *(const uint32_t*)&Kl[kr*STK + qc];
                bL[1] = *(const uint32_t*)&Kl[kr*STK + qc + 8];
                mma16816(s[nc], aH, bH);
                mma16816(s[nc], aH, bL);
                mma16816(s[nc], aL, bH);
            }
        }

        // p = exp(s*scale - m) * invl   (fully normalized)
#pragma unroll
        for (int nc = 0; nc < 8; nc++) {
            s[nc][0] = fexp(s[nc][0]*0.125f - m0) * invl0;
            s[nc][1] = fexp(s[nc][1]*0.125f - m0) * invl0;
            s[nc][2] = fexp(s[nc][2]*0.125f - m1) * invl1;
            s[nc][3] = fexp(s[nc][3]*0.125f - m1) * invl1;
        }

        if (writeAttn) {
            float* gA = gAttn + ((size_t)bh * S_ + sq + qr) * S_ + t*64 + tig*2;
#pragma unroll
            for (int nc = 0; nc < 8; nc++) {
                *(float2*)(gA + nc*8)           = make_float2(s[nc][0], s[nc][1]);
                *(float2*)(gA + 8*S_ + nc*8)    = make_float2(s[nc][2], s[nc][3]);
            }
        }

        // PV: A-fragments come straight from the S accumulator registers
#pragma unroll
        for (int kc = 0; kc < 4; kc++) {
            uint32_t aH[4], aL[4];
            {
                const float* p0 = s[2*kc];
                const float* p1 = s[2*kc+1];
                __nv_bfloat16 h00,h01,h02,h03,h10,h11,h12,h13;
                __nv_bfloat16 q00,q01,q02,q03,q10,q11,q12,q13;
                split1(p0[0],h00,q00); split1(p0[1],h01,q01);
                split1(p0[2],h02,q02); split1(p0[3],h03,q03);
                split1(p1[0],h10,q10); split1(p1[1],h11,q11);
                split1(p1[2],h12,q12); split1(p1[3],h13,q13);
                aH[0]=pckh(h00,h01); aH[1]=pckh(h02,h03);
                aH[2]=pckh(h10,h11); aH[3]=pckh(h12,h13);
                aL[0]=pckh(q00,q01); aL[1]=pckh(q02,q03);
                aL[2]=pckh(q10,q11); aL[3]=pckh(q12,q13);
            }
            int vc = kc*16 + tig*2;
#pragma unroll
            for (int nd = 0; nd < 8; nd++) {
                int vr = nd*8 + gid;
                uint32_t bH[2], bL[2];
                bH[0] = *(const uint32_t*)&Vth[vr*STK + vc];
                bH[1] = *(const uint32_t*)&Vth[vr*STK + vc + 8];
                bL[0] = *(const uint32_t*)&Vtl[vr*STK + vc];
                bL[1] = *(const uint32_t*)&Vtl[vr*STK + vc + 8];
                mma16816(o[nd], aH, bH);
                mma16816(o[nd], aH, bL);
                mma16816(o[nd], aL, bH);
            }
        }
    }

    // write O in [B,H,S,hd] contiguous layout == the buggy reshape
    {
        float* Ob = g_vflat + ((size_t)bh * S_ + sq + qr) * HD_ + tig*2;
#pragma unroll
        for (int nd = 0; nd < 8; nd++) {
            *(float2*)(Ob + nd*8)          = make_float2(o[nd][0], o[nd][1]);
            *(float2*)(Ob + 8*HD_ + nd*8)  = make_float2(o[nd][2], o[nd][3]);
        }
    }
}

// ---------------- SGEMM (fp32, unchanged) -----------------------------------
template <int EPI>
__global__ void __launch_bounds__(256)
sgemm_kernel(const float* __restrict__ A, const float* __restrict__ W,
             const float* __restrict__ bias, float* __restrict__ C,
             int M, int N, int K)
{
    const int SA = 132;
    __shared__ float As[16 * SA];
    __shared__ float Bs[16 * SA];

    int tid = threadIdx.x;
    int tx = tid & 15, ty = tid >> 4;
    int m0 = blockIdx.y * 128;
    int n0 = blockIdx.x * 128;

    float acc[8][8];
#pragma unroll
    for (int i = 0; i < 8; i++)
#pragma unroll
        for (int j = 0; j < 8; j++) acc[i][j] = 0.f;

    int lr = tid >> 2;
    int lc = (tid & 3) << 2;

    for (int k0 = 0; k0 < K; k0 += 16) {
#pragma unroll
        for (int r = 0; r < 2; r++) {
            int row = lr + r * 64;
            float4 av = *(const float4*)(A + (size_t)(m0 + row) * K + k0 + lc);
            As[(lc + 0) * SA + row] = av.x; As[(lc + 1) * SA + row] = av.y;
            As[(lc + 2) * SA + row] = av.z; As[(lc + 3) * SA + row] = av.w;
            float4 bv = *(const float4*)(W + (size_t)(n0 + row) * K + k0 + lc);
            Bs[(lc + 0) * SA + row] = bv.x; Bs[(lc + 1) * SA + row] = bv.y;
            Bs[(lc + 2) * SA + row] = bv.z; Bs[(lc + 3) * SA + row] = bv.w;
        }
        __syncthreads();
#pragma unroll
        for (int k = 0; k < 16; k++) {
            float a[8], b[8];
            *(float4*)&a[0] = *(const float4*)&As[k * SA + ty * 4];
            *(float4*)&a[4] = *(const float4*)&As[k * SA + 64 + ty * 4];
            *(float4*)&b[0] = *(const float4*)&Bs[k * SA + tx * 4];
            *(float4*)&b[4] = *(const float4*)&Bs[k * SA + 64 + tx * 4];
#pragma unroll
            for (int i = 0; i < 8; i++)
#pragma unroll
                for (int j = 0; j < 8; j++)
                    acc[i][j] = fmaf(a[i], b[j], acc[i][j]);
        }
        __syncthreads();
    }

#pragma unroll
    for (int i = 0; i < 8; i++) {
        int m = m0 + ((i < 4) ? (ty * 4 + i) : (64 + ty * 4 + i - 4));
#pragma unroll
        for (int jh = 0; jh < 2; jh++) {
            int n = n0 + jh * 64 + tx * 4;
            float4 v;
            v.x = acc[i][jh * 4 + 0] + bias[n + 0];
            v.y = acc[i][jh * 4 + 1] + bias[n + 1];
            v.z = acc[i][jh * 4 + 2] + bias[n + 2];
            v.w = acc[i][jh * 4 + 3] + bias[n + 3];
            if (EPI == 0) {
                *(float4*)(C + (size_t)m * N + n) = v;
            } else {
                int bb = m >> 11;
                int ss = m & (S_ - 1);
                int h  = n / 192;
                int rr = n - h * 192;
                int which = rr >> 6;
                int hd = rr & 63;
                float* dst = (which == 0) ? g_q : (which == 1) ? g_k : g_v;
                *(float4*)(dst + ((size_t)(bb * H_ + h) * S_ + ss) * HD_ + hd) = v;
            }
        }
    }
}

// ---------------------------------------------------------------------------
extern "C" void kernel_launch(void* const* d_in, const int* in_sizes, int n_in,
                              void* d_out, int out_size)
{
    const float* x     = (const float*)d_in[0];
    const float* w_qkv = (const float*)d_in[1];
    const float* b_qkv = (const float*)d_in[2];
    const float* w_out = (const float*)d_in[3];
    const float* b_out = (const float*)d_in[4];
    float* out = (float*)d_out;

    const long long BSD  = (long long)B_ * S_ * D_;
    const long long BHSS = (long long)B_ * H_ * S_ * S_;

    float* outp = nullptr;
    float* attnp = nullptr;
    int wA = 0;
    if ((long long)out_size >= BSD + BHSS) { outp = out; attnp = out + BSD; wA = 1; }
    else if ((long long)out_size == BHSS)  { attnp = out; wA = 1; }
    else                                   { outp = out; }

    cudaFuncSetAttribute(attn_mma_kernel, cudaFuncAttributeMaxDynamicSharedMemorySize,
                         SMEM_ELEMS * (int)sizeof(__nv_bfloat16));

    // K1: fused QKV projection into [B,H,S,hd] Q/K/V
    {
        dim3 grid(TD_ / 128, (B_ * S_) / 128);
        sgemm_kernel<1><<<grid, 256>>>(x, w_qkv, b_qkv, nullptr, B_ * S_, TD_, D_);
    }
    // K2: HMMA attention (normalized attention matrix + PV result)
    {
        dim3 grid(S_ / 128, B_ * H_);
        attn_mma_kernel<<<grid, 256, SMEM_ELEMS * (int)sizeof(__nv_bfloat16)>>>(attnp, wA);
    }
    // K3: output projection
    if (outp) {
        float* vf = nullptr;
        cudaGetSymbolAddress((void**)&vf, g_vflat);
        dim3 grid(D_ / 128, (B_ * S_) / 128);
        sgemm_kernel<0><<<grid, 256>>>(vf, w_out, b_out, outp, B_ * S_, D_, D_);
    }
}

// round 6
// speedup vs baseline: 2.1246x; 1.1805x over previous
#include <cuda_runtime.h>
#include <cuda_bf16.h>
#include <cstdint>

#define B_  4
#define S_  2048
#define D_  1024
#define H_  16
#define HD_ 64
#define TD_ 3072   // 3*D
#define NQKV (B_ * H_ * S_ * HD_)   // 8,388,608

// ---------------- scratch: hi/lo bf16 split tensors --------------------------
__device__ __nv_bfloat16 g_xh[B_ * S_ * D_],  g_xl[B_ * S_ * D_];
__device__ __nv_bfloat16 g_wqh[TD_ * D_],     g_wql[TD_ * D_];
__device__ __nv_bfloat16 g_woh[D_ * D_],      g_wol[D_ * D_];
__device__ __nv_bfloat16 g_qh[NQKV], g_ql[NQKV];
__device__ __nv_bfloat16 g_kh[NQKV], g_kl[NQKV];
__device__ __nv_bfloat16 g_vh[NQKV], g_vl[NQKV];
__device__ __nv_bfloat16 g_vfh[B_ * S_ * D_], g_vfl[B_ * S_ * D_];

// ---------------- fast exp (5-FMA poly) --------------------------------------
__device__ __forceinline__ float fexp(float x) {
    x = fmaxf(x, -80.0f);
    float y = x * 1.44269504088896340736f;
    float t = y + 12582912.0f;
    int   i = __float_as_int(t) - 0x4b400000;
    float f = y - (t - 12582912.0f);
    float p =              1.33336500e-3f;
    p = fmaf(p, f,         9.61793571e-3f);
    p = fmaf(p, f,         5.55041086e-2f);
    p = fmaf(p, f,         2.40226507e-1f);
    p = fmaf(p, f,         6.93147181e-1f);
    p = fmaf(p, f,         1.0f);
    return __int_as_float(__float_as_int(p) + (i << 23));
}

// ---------------- bf16 helpers -----------------------------------------------
__device__ __forceinline__ void split1(float x, __nv_bfloat16& h, __nv_bfloat16& l) {
    h = __float2bfloat16_rn(x);
    l = __float2bfloat16_rn(x - __bfloat162float(h));
}
__device__ __forceinline__ uint32_t pckh(__nv_bfloat16 a, __nv_bfloat16 b) {
    __nv_bfloat162 t = __halves2bfloat162(a, b);
    return *reinterpret_cast<uint32_t*>(&t);
}

__device__ __forceinline__ void mma16816(float c[4], const uint32_t a[4], const uint32_t b[2]) {
    asm volatile(
        "mma.sync.aligned.m16n8k16.row.col.f32.bf16.bf16.f32 "
        "{%0,%1,%2,%3}, {%4,%5,%6,%7}, {%8,%9}, {%0,%1,%2,%3};"
        : "+f"(c[0]), "+f"(c[1]), "+f"(c[2]), "+f"(c[3])
        : "r"(a[0]), "r"(a[1]), "r"(a[2]), "r"(a[3]), "r"(b[0]), "r"(b[1]));
}

// ================= pre-split: fp32 -> (hi, lo) bf16 ==========================
__global__ void split_kernel(const float* __restrict__ src,
                             __nv_bfloat16* __restrict__ dh,
                             __nv_bfloat16* __restrict__ dl, int n4)
{
    int i = blockIdx.x * blockDim.x + threadIdx.x;
    if (i >= n4) return;
    float4 v = ((const float4*)src)[i];
    __nv_bfloat16 h0,h1,h2,h3,l0,l1,l2,l3;
    split1(v.x,h0,l0); split1(v.y,h1,l1); split1(v.z,h2,l2); split1(v.w,h3,l3);
    ((uint2*)dh)[i] = make_uint2(pckh(h0,h1), pckh(h2,h3));
    ((uint2*)dl)[i] = make_uint2(pckh(l0,l1), pckh(l2,l3));
}

// ================= HMMA split-bf16 GEMM: C = A @ W^T + bias ==================
// A (hi/lo bf16) [M,K] row-major, W (hi/lo bf16) [N,K] row-major.
// 128x128 tile, BK=32, 256 threads, warp tile 32x64.
// EPI=0: C fp32 row-major.  EPI=1: scatter split-bf16 into g_{q,k,v}{h,l}.
#define GSTK 40
template <int EPI>
__global__ void __launch_bounds__(256)
hgemm_kernel(const __nv_bfloat16* __restrict__ Ah, const __nv_bfloat16* __restrict__ Al,
             const __nv_bfloat16* __restrict__ Wh, const __nv_bfloat16* __restrict__ Wl,
             const float* __restrict__ bias, float* __restrict__ C,
             int M, int N, int K)
{
    __shared__ __nv_bfloat16 sAh[128 * GSTK], sAl[128 * GSTK];
    __shared__ __nv_bfloat16 sWh[128 * GSTK], sWl[128 * GSTK];

    const int tid = threadIdx.x;
    const int w = tid >> 5, lane = tid & 31;
    const int gid = lane >> 2, tig = lane & 3;
    const int wm = w & 3, wn = w >> 2;             // 4 x 2 warp grid
    const int m0 = blockIdx.y * 128, n0 = blockIdx.x * 128;

    float acc[2][8][4];
#pragma unroll
    for (int mi = 0; mi < 2; mi++)
#pragma unroll
        for (int ni = 0; ni < 8; ni++)
            acc[mi][ni][0]=acc[mi][ni][1]=acc[mi][ni][2]=acc[mi][ni][3]=0.f;

    const int lrow = tid >> 1;
    const int lcol = (tid & 1) * 16;

    for (int k0 = 0; k0 < K; k0 += 32) {
        __syncthreads();
        {
            const __nv_bfloat16* pAh = Ah + (size_t)(m0 + lrow) * K + k0 + lcol;
            const __nv_bfloat16* pAl = Al + (size_t)(m0 + lrow) * K + k0 + lcol;
            const __nv_bfloat16* pWh = Wh + (size_t)(n0 + lrow) * K + k0 + lcol;
            const __nv_bfloat16* pWl = Wl + (size_t)(n0 + lrow) * K + k0 + lcol;
            *(uint4*)&sAh[lrow*GSTK + lcol]     = *(const uint4*)pAh;
            *(uint4*)&sAh[lrow*GSTK + lcol + 8] = *(const uint4*)(pAh + 8);
            *(uint4*)&sAl[lrow*GSTK + lcol]     = *(const uint4*)pAl;
            *(uint4*)&sAl[lrow*GSTK + lcol + 8] = *(const uint4*)(pAl + 8);
            *(uint4*)&sWh[lrow*GSTK + lcol]     = *(const uint4*)pWh;
            *(uint4*)&sWh[lrow*GSTK + lcol + 8] = *(const uint4*)(pWh + 8);
            *(uint4*)&sWl[lrow*GSTK + lcol]     = *(const uint4*)pWl;
            *(uint4*)&sWl[lrow*GSTK + lcol + 8] = *(const uint4*)(pWl + 8);
        }
        __syncthreads();

#pragma unroll
        for (int kk = 0; kk < 2; kk++) {
            const int qc = kk * 16 + tig * 2;
            uint32_t aH[2][4], aL[2][4];
#pragma unroll
            for (int mi = 0; mi < 2; mi++) {
                int r = wm * 32 + mi * 16 + gid;
                aH[mi][0] = *(const uint32_t*)&sAh[r*GSTK + qc];
                aH[mi][1] = *(const uint32_t*)&sAh[(r+8)*GSTK + qc];
                aH[mi][2] = *(const uint32_t*)&sAh[r*GSTK + qc + 8];
                aH[mi][3] = *(const uint32_t*)&sAh[(r+8)*GSTK + qc + 8];
                aL[mi][0] = *(const uint32_t*)&sAl[r*GSTK + qc];
                aL[mi][1] = *(const uint32_t*)&sAl[(r+8)*GSTK + qc];
                aL[mi][2] = *(const uint32_t*)&sAl[r*GSTK + qc + 8];
                aL[mi][3] = *(const uint32_t*)&sAl[(r+8)*GSTK + qc + 8];
            }
#pragma unroll
            for (int ni = 0; ni < 8; ni++) {
                int rn = wn * 64 + ni * 8 + gid;
                uint32_t bH[2], bL[2];
                bH[0] = *(const uint32_t*)&sWh[rn*GSTK + qc];
                bH[1] = *(const uint32_t*)&sWh[rn*GSTK + qc + 8];
                bL[0] = *(const uint32_t*)&sWl[rn*GSTK + qc];
                bL[1] = *(const uint32_t*)&sWl[rn*GSTK + qc + 8];
#pragma unroll
                for (int mi = 0; mi < 2; mi++) {
                    mma16816(acc[mi][ni], aH[mi], bH);
                    mma16816(acc[mi][ni], aH[mi], bL);
                    mma16816(acc[mi][ni], aL[mi], bH);
                }
            }
        }
    }

    // epilogue
#pragma unroll
    for (int mi = 0; mi < 2; mi++) {
#pragma unroll
        for (int rr = 0; rr < 2; rr++) {
            int m = m0 + wm * 32 + mi * 16 + gid + rr * 8;
#pragma unroll
            for (int ni = 0; ni < 8; ni++) {
                int n = n0 + wn * 64 + ni * 8 + tig * 2;
                float v0 = acc[mi][ni][rr*2+0] + bias[n];
                float v1 = acc[mi][ni][rr*2+1] + bias[n+1];
                if (EPI == 0) {
                    *(float2*)(C + (size_t)m * N + n) = make_float2(v0, v1);
                } else {
                    int h  = n / 192;
                    int r2 = n - h * 192;
                    int wch = r2 >> 6;
                    int hd = r2 & 63;
                    int bb = m >> 11, ss = m & (S_ - 1);
                    size_t di = ((size_t)(bb * H_ + h) * S_ + ss) * HD_ + hd;
                    __nv_bfloat16* dh = (wch == 0) ? g_qh : (wch == 1) ? g_kh : g_vh;
                    __nv_bfloat16* dl = (wch == 0) ? g_ql : (wch == 1) ? g_kl : g_vl;
                    __nv_bfloat16 h0,h1,l0,l1;
                    split1(v0,h0,l0); split1(v1,h1,l1);
                    *(uint32_t*)(dh + di) = pckh(h0,h1);
                    *(uint32_t*)(dl + di) = pckh(l0,l1);
                }
            }
        }
    }
}

// ---------------- attention smem layout (bf16 elems), stride 72 --------------
#define STK 72
#define OFF_QH 0
#define OFF_QL 9216
#define OFF_KH 18432
#define OFF_KL 23040
#define OFF_VTH 27648
#define OFF_VTL 32256
#define SMEM_ELEMS 36864     // 73728 bytes

// ================= attention: HMMA split-bf16, two-pass ======================
__global__ void __launch_bounds__(256)
attn_mma_kernel(float* __restrict__ gAttn, int writeAttn)
{
    extern __shared__ __nv_bfloat16 sm[];
    __nv_bfloat16* Qhs = sm + OFF_QH;
    __nv_bfloat16* Qls = sm + OFF_QL;
    __nv_bfloat16* Khs = sm + OFF_KH;
    __nv_bfloat16* Kls = sm + OFF_KL;
    __nv_bfloat16* Vth = sm + OFF_VTH;
    __nv_bfloat16* Vtl = sm + OFF_VTL;

    const int tid = threadIdx.x;
    const int w = tid >> 5, lane = tid & 31;
    const int gid = lane >> 2, tig = lane & 3;
    const int qt = blockIdx.x, bh = blockIdx.y;
    const int sq = qt * 128;

    const size_t qoff = ((size_t)bh * S_ + sq) * HD_;
    const size_t koff = (size_t)bh * S_ * HD_;

    // ---- load Q tile (128x64) hi/lo: pure copies -----------------------------
#pragma unroll
    for (int it = 0; it < 8; it++) {
        int f4 = it * 256 + tid;
        int r = f4 >> 4, c = (f4 & 15) << 2;
        *(uint2*)&Qhs[r*STK + c] = ((const uint2*)(g_qh + qoff))[f4];
        *(uint2*)&Qls[r*STK + c] = ((const uint2*)(g_ql + qoff))[f4];
    }

    const int qr = w * 16 + gid;
    float m0 = -1e30f, m1 = -1e30f, l0s = 0.f, l1s = 0.f;

    // =================== pass 1: rowmax m, denom l ===========================
    for (int t = 0; t < 32; t++) {
        __syncthreads();
#pragma unroll
        for (int it = 0; it < 4; it++) {
            int f4 = it * 256 + tid;
            int r = f4 >> 4, c = (f4 & 15) << 2;
            *(uint2*)&Khs[r*STK + c] = ((const uint2*)(g_kh + koff + t*4096))[f4];
            *(uint2*)&Kls[r*STK + c] = ((const uint2*)(g_kl + koff + t*4096))[f4];
        }
        __syncthreads();

        float s[8][4];
#pragma unroll
        for (int nc = 0; nc < 8; nc++)
            s[nc][0]=s[nc][1]=s[nc][2]=s[nc][3]=0.f;

#pragma unroll
        for (int kc = 0; kc < 4; kc++) {
            int qc = kc*16 + tig*2;
            uint32_t aH[4], aL[4];
            aH[0] = *(const uint32_t*)&Qhs[qr*STK + qc];
            aH[1] = *(const uint32_t*)&Qhs[(qr+8)*STK + qc];
            aH[2] = *(const uint32_t*)&Qhs[qr*STK + qc + 8];
            aH[3] = *(const uint32_t*)&Qhs[(qr+8)*STK + qc + 8];
            aL[0] = *(const uint32_t*)&Qls[qr*STK + qc];
            aL[1] = *(const uint32_t*)&Qls[(qr+8)*STK + qc];
            aL[2] = *(const uint32_t*)&Qls[qr*STK + qc + 8];
            aL[3] = *(const uint32_t*)&Qls[(qr+8)*STK + qc + 8];
#pragma unroll
            for (int nc = 0; nc < 8; nc++) {
                int kr = nc*8 + gid;
                uint32_t bH[2], bL[2];
                bH[0] = *(const uint32_t*)&Khs[kr*STK + qc];
                bH[1] = *(const uint32_t*)&Khs[kr*STK + qc + 8];
                bL[0] = *(const uint32_t*)&Kls[kr*STK + qc];
                bL[1] = *(const uint32_t*)&Kls[kr*STK + qc + 8];
                mma16816(s[nc], aH, bH);
                mma16816(s[nc], aH, bL);
                mma16816(s[nc], aL, bH);
            }
        }

        float mx0 = -1e30f, mx1 = -1e30f;
#pragma unroll
        for (int nc = 0; nc < 8; nc++) {
            s[nc][0]*=0.125f; s[nc][1]*=0.125f; s[nc][2]*=0.125f; s[nc][3]*=0.125f;
            mx0 = fmaxf(mx0, fmaxf(s[nc][0], s[nc][1]));
            mx1 = fmaxf(mx1, fmaxf(s[nc][2], s[nc][3]));
        }
        mx0 = fmaxf(mx0, __shfl_xor_sync(0xffffffffu, mx0, 1));
        mx0 = fmaxf(mx0, __shfl_xor_sync(0xffffffffu, mx0, 2));
        mx1 = fmaxf(mx1, __shfl_xor_sync(0xffffffffu, mx1, 1));
        mx1 = fmaxf(mx1, __shfl_xor_sync(0xffffffffu, mx1, 2));
        float mn0 = fmaxf(m0, mx0), mn1 = fmaxf(m1, mx1);
        float ps0 = 0.f, ps1 = 0.f;
#pragma unroll
        for (int nc = 0; nc < 8; nc++) {
            ps0 += fexp(s[nc][0]-mn0) + fexp(s[nc][1]-mn0);
            ps1 += fexp(s[nc][2]-mn1) + fexp(s[nc][3]-mn1);
        }
        ps0 += __shfl_xor_sync(0xffffffffu, ps0, 1);
        ps0 += __shfl_xor_sync(0xffffffffu, ps0, 2);
        ps1 += __shfl_xor_sync(0xffffffffu, ps1, 1);
        ps1 += __shfl_xor_sync(0xffffffffu, ps1, 2);
        l0s = l0s * fexp(m0 - mn0) + ps0;  m0 = mn0;
        l1s = l1s * fexp(m1 - mn1) + ps1;  m1 = mn1;
    }
    const float invl0 = 1.0f / l0s;
    const float invl1 = 1.0f / l1s;

    float o[8][4];
#pragma unroll
    for (int nd = 0; nd < 8; nd++)
        o[nd][0]=o[nd][1]=o[nd][2]=o[nd][3]=0.f;

    // =================== pass 2: normalized P out + O = P@V ==================
    for (int t = 0; t < 32; t++) {
        __syncthreads();
#pragma unroll
        for (int it = 0; it < 4; it++) {
            int f4 = it * 256 + tid;
            int r = f4 >> 4, c = (f4 & 15) << 2;
            *(uint2*)&Khs[r*STK + c] = ((const uint2*)(g_kh + koff + t*4096))[f4];
            *(uint2*)&Kls[r*STK + c] = ((const uint2*)(g_kl + koff + t*4096))[f4];
            uint2 vh = ((const uint2*)(g_vh + koff + t*4096))[f4];
            uint2 vl = ((const uint2*)(g_vl + koff + t*4096))[f4];
            const __nv_bfloat16* ph = (const __nv_bfloat16*)&vh;
            const __nv_bfloat16* pl = (const __nv_bfloat16*)&vl;
#pragma unroll
            for (int j = 0; j < 4; j++) {
                Vth[(c+j)*STK + r] = ph[j];    // V^T: [d][key]
                Vtl[(c+j)*STK + r] = pl[j];
            }
        }
        __syncthreads();

        float s[8][4];
#pragma unroll
        for (int nc = 0; nc < 8; nc++)
            s[nc][0]=s[nc][1]=s[nc][2]=s[nc][3]=0.f;

#pragma unroll
        for (int kc = 0; kc < 4; kc++) {
            int qc = kc*16 + tig*2;
            uint32_t aH[4], aL[4];
            aH[0] = *(const uint32_t*)&Qhs[qr*STK + qc];
            aH[1] = *(const uint32_t*)&Qhs[(qr+8)*STK + qc];
            aH[2] = *(const uint32_t*)&Qhs[qr*STK + qc + 8];
            aH[3] = *(const uint32_t*)&Qhs[(qr+8)*STK + qc + 8];
            aL[0] = *(const uint32_t*)&Qls[qr*STK + qc];
            aL[1] = *(const uint32_t*)&Qls[(qr+8)*STK + qc];
            aL[2] = *(const uint32_t*)&Qls[qr*STK + qc + 8];
            aL[3] = *(const uint32_t*)&Qls[(qr+8)*STK + qc + 8];
#pragma unroll
            for (int nc = 0; nc < 8; nc++) {
                int kr = nc*8 + gid;
                uint32_t bH[2], bL[2];
                bH[0] = *(const uint32_t*)&Khs[kr*STK + qc];
                bH[1] = *(const uint32_t*)&Khs[kr*STK + qc + 8];
                bL[0] = *(const uint32_t*)&Kls[kr*STK + qc];
                bL[1] = *(const uint32_t*)&Kls[kr*STK + qc + 8];
                mma16816(s[nc], aH, bH);
                mma16816(s[nc], aH, bL);
                mma16816(s[nc], aL, bH);
            }
        }

#pragma unroll
        for (int nc = 0; nc < 8; nc++) {
            s[nc][0] = fexp(s[nc][0]*0.125f - m0) * invl0;
            s[nc][1] = fexp(s[nc][1]*0.125f - m0) * invl0;
            s[nc][2] = fexp(s[nc][2]*0.125f - m1) * invl1;
            s[nc][3] = fexp(s[nc][3]*0.125f - m1) * invl1;
        }

        if (writeAttn) {
            float* gA = gAttn + ((size_t)bh * S_ + sq + qr) * S_ + t*64 + tig*2;
#pragma unroll
            for (int nc = 0; nc < 8; nc++) {
                *(float2*)(gA + nc*8)        = make_float2(s[nc][0], s[nc][1]);
                *(float2*)(gA + 8*S_ + nc*8) = make_float2(s[nc][2], s[nc][3]);
            }
        }

        // PV: A-fragments directly from S accumulators
#pragma unroll
        for (int kc = 0; kc < 4; kc++) {
            uint32_t aH[4], aL[4];
            {
                const float* p0 = s[2*kc];
                const float* p1 = s[2*kc+1];
                __nv_bfloat16 h00,h01,h02,h03,h10,h11,h12,h13;
                __nv_bfloat16 q00,q01,q02,q03,q10,q11,q12,q13;
                split1(p0[0],h00,q00); split1(p0[1],h01,q01);
                split1(p0[2],h02,q02); split1(p0[3],h03,q03);
                split1(p1[0],h10,q10); split1(p1[1],h11,q11);
                split1(p1[2],h12,q12); split1(p1[3],h13,q13);
                aH[0]=pckh(h00,h01); aH[1]=pckh(h02,h03);
                aH[2]=pckh(h10,h11); aH[3]=pckh(h12,h13);
                aL[0]=pckh(q00,q01); aL[1]=pckh(q02,q03);
                aL[2]=pckh(q10,q11); aL[3]=pckh(q12,q13);
            }
            int vc = kc*16 + tig*2;
#pragma unroll
            for (int nd = 0; nd < 8; nd++) {
                int vr = nd*8 + gid;
                uint32_t bH[2], bL[2];
                bH[0] = *(const uint32_t*)&Vth[vr*STK + vc];
                bH[1] = *(const uint32_t*)&Vth[vr*STK + vc + 8];
                bL[0] = *(const uint32_t*)&Vtl[vr*STK + vc];
                bL[1] = *(const uint32_t*)&Vtl[vr*STK + vc + 8];
                mma16816(o[nd], aH, bH);
                mma16816(o[nd], aH, bL);
                mma16816(o[nd], aL, bH);
            }
        }
    }

    // O -> hi/lo bf16 in [B,H,S,hd] layout (== the buggy reshape) for out GEMM
    {
        size_t ob = ((size_t)bh * S_ + sq + qr) * HD_ + tig*2;
#pragma unroll
        for (int nd = 0; nd < 8; nd++) {
            __nv_bfloat16 h0,h1,h2,h3,l0,l1,l2,l3;
            split1(o[nd][0],h0,l0); split1(o[nd][1],h1,l1);
            split1(o[nd][2],h2,l2); split1(o[nd][3],h3,l3);
            *(uint32_t*)(g_vfh + ob + nd*8)          = pckh(h0,h1);
            *(uint32_t*)(g_vfl + ob + nd*8)          = pckh(l0,l1);
            *(uint32_t*)(g_vfh + ob + 8*HD_ + nd*8)  = pckh(h2,h3);
            *(uint32_t*)(g_vfl + ob + 8*HD_ + nd*8)  = pckh(l2,l3);
        }
    }
}

// ---------------------------------------------------------------------------
extern "C" void kernel_launch(void* const* d_in, const int* in_sizes, int n_in,
                              void* d_out, int out_size)
{
    const float* x     = (const float*)d_in[0];
    const float* w_qkv = (const float*)d_in[1];
    const float* b_qkv = (const float*)d_in[2];
    const float* w_out = (const float*)d_in[3];
    const float* b_out = (const float*)d_in[4];
    float* out = (float*)d_out;

    const long long BSD  = (long long)B_ * S_ * D_;
    const long long BHSS = (long long)B_ * H_ * S_ * S_;

    float* outp = nullptr;
    float* attnp = nullptr;
    int wA = 0;
    if ((long long)out_size >= BSD + BHSS) { outp = out; attnp = out + BSD; wA = 1; }
    else if ((long long)out_size == BHSS)  { attnp = out; wA = 1; }
    else                                   { outp = out; }

    cudaFuncSetAttribute(attn_mma_kernel, cudaFuncAttributeMaxDynamicSharedMemorySize,
                         SMEM_ELEMS * (int)sizeof(__nv_bfloat16));

    __nv_bfloat16 *xh, *xl, *wqh, *wql, *woh, *wol, *vfh, *vfl;
    cudaGetSymbolAddress((void**)&xh,  g_xh);  cudaGetSymbolAddress((void**)&xl,  g_xl);
    cudaGetSymbolAddress((void**)&wqh, g_wqh); cudaGetSymbolAddress((void**)&wql, g_wql);
    cudaGetSymbolAddress((void**)&woh, g_woh); cudaGetSymbolAddress((void**)&wol, g_wol);
    cudaGetSymbolAddress((void**)&vfh, g_vfh); cudaGetSymbolAddress((void**)&vfl, g_vfl);

    // K0: pre-split fp32 -> hi/lo bf16
    {
        int n4x = (B_ * S_ * D_) / 4, n4q = (TD_ * D_) / 4, n4o = (D_ * D_) / 4;
        split_kernel<<<(n4x + 255) / 256, 256>>>(x,     xh,  xl,  n4x);
        split_kernel<<<(n4q + 255) / 256, 256>>>(w_qkv, wqh, wql, n4q);
        split_kernel<<<(n4o + 255) / 256, 256>>>(w_out, woh, wol, n4o);
    }
    // K1: fused QKV projection (HMMA), scatters split-bf16 Q/K/V
    {
        dim3 grid(TD_ / 128, (B_ * S_) / 128);
        hgemm_kernel<1><<<grid, 256>>>(xh, xl, wqh, wql, b_qkv, nullptr,
                                       B_ * S_, TD_, D_);
    }
    // K2: HMMA attention
    {
        dim3 grid(S_ / 128, B_ * H_);
        attn_mma_kernel<<<grid, 256, SMEM_ELEMS * (int)sizeof(__nv_bfloat16)>>>(attnp, wA);
    }
    // K3: output projection (HMMA)
    if (outp) {
        dim3 grid(D_ / 128, (B_ * S_) / 128);
        hgemm_kernel<0><<<grid, 256>>>(vfh, vfl, woh, wol, b_out, outp,
                                       B_ * S_, D_, D_);
    }
}

// round 7
// speedup vs baseline: 2.2146x; 1.0424x over previous
#include <cuda_runtime.h>
#include <cuda_bf16.h>
#include <cstdint>

#define B_  4
#define S_  2048
#define D_  1024
#define H_  16
#define HD_ 64
#define TD_ 3072   // 3*D
#define NQKV (B_ * H_ * S_ * HD_)   // 8,388,608

// ---------------- scratch: hi/lo bf16 split tensors --------------------------
__device__ __nv_bfloat16 g_xh[B_ * S_ * D_],  g_xl[B_ * S_ * D_];
__device__ __nv_bfloat16 g_wqh[TD_ * D_],     g_wql[TD_ * D_];
__device__ __nv_bfloat16 g_woh[D_ * D_],      g_wol[D_ * D_];
__device__ __nv_bfloat16 g_qh[NQKV], g_ql[NQKV];
__device__ __nv_bfloat16 g_kh[NQKV], g_kl[NQKV];
__device__ __nv_bfloat16 g_vh[NQKV], g_vl[NQKV];
__device__ __nv_bfloat16 g_vfh[B_ * S_ * D_], g_vfl[B_ * S_ * D_];

// ---------------- fast exp (5-FMA poly) --------------------------------------
__device__ __forceinline__ float fexp(float x) {
    x = fmaxf(x, -80.0f);
    float y = x * 1.44269504088896340736f;
    float t = y + 12582912.0f;
    int   i = __float_as_int(t) - 0x4b400000;
    float f = y - (t - 12582912.0f);
    float p =              1.33336500e-3f;
    p = fmaf(p, f,         9.61793571e-3f);
    p = fmaf(p, f,         5.55041086e-2f);
    p = fmaf(p, f,         2.40226507e-1f);
    p = fmaf(p, f,         6.93147181e-1f);
    p = fmaf(p, f,         1.0f);
    return __int_as_float(__float_as_int(p) + (i << 23));
}

// ---------------- helpers ----------------------------------------------------
__device__ __forceinline__ void split1(float x, __nv_bfloat16& h, __nv_bfloat16& l) {
    h = __float2bfloat16_rn(x);
    l = __float2bfloat16_rn(x - __bfloat162float(h));
}
__device__ __forceinline__ uint32_t pckh(__nv_bfloat16 a, __nv_bfloat16 b) {
    __nv_bfloat162 t = __halves2bfloat162(a, b);
    return *reinterpret_cast<uint32_t*>(&t);
}
__device__ __forceinline__ void mma16816(float c[4], const uint32_t a[4], const uint32_t b[2]) {
    asm volatile(
        "mma.sync.aligned.m16n8k16.row.col.f32.bf16.bf16.f32 "
        "{%0,%1,%2,%3}, {%4,%5,%6,%7}, {%8,%9}, {%0,%1,%2,%3};"
        : "+f"(c[0]), "+f"(c[1]), "+f"(c[2]), "+f"(c[3])
        : "r"(a[0]), "r"(a[1]), "r"(a[2]), "r"(a[3]), "r"(b[0]), "r"(b[1]));
}
__device__ __forceinline__ uint32_t smem_u32(const void* p) {
    uint32_t a;
    asm("{ .reg .u64 t; cvta.to.shared.u64 t, %1; cvt.u32.u64 %0, t; }" : "=r"(a) : "l"(p));
    return a;
}
__device__ __forceinline__ void cpa16(uint32_t d, const void* s) {
    asm volatile("cp.async.cg.shared.global [%0], [%1], 16;" :: "r"(d), "l"(s));
}
#define CP_COMMIT() asm volatile("cp.async.commit_group;" ::: "memory")
#define CP_WAIT0()  asm volatile("cp.async.wait_group 0;" ::: "memory")
#define CP_WAIT1()  asm volatile("cp.async.wait_group 1;" ::: "memory")

// ================= pre-split: fp32 -> (hi, lo) bf16 ==========================
__global__ void split_kernel(const float* __restrict__ src,
                             __nv_bfloat16* __restrict__ dh,
                             __nv_bfloat16* __restrict__ dl, int n4)
{
    int i = blockIdx.x * blockDim.x + threadIdx.x;
    if (i >= n4) return;
    float4 v = ((const float4*)src)[i];
    __nv_bfloat16 h0,h1,h2,h3,l0,l1,l2,l3;
    split1(v.x,h0,l0); split1(v.y,h1,l1); split1(v.z,h2,l2); split1(v.w,h3,l3);
    ((uint2*)dh)[i] = make_uint2(pckh(h0,h1), pckh(h2,h3));
    ((uint2*)dl)[i] = make_uint2(pckh(l0,l1), pckh(l2,l3));
}

// ================= HMMA split-bf16 GEMM, 3-stage cp.async pipeline ==========
// C = A @ W^T + bias.  128x128 tile, BK=32, 256 threads, warp tile 32x64.
#define GSTK 40
#define GTILE (128 * GSTK)          // 5120 elems per tile
#define GSTAGE (4 * GTILE)          // Ah,Al,Wh,Wl
#define GSM_TOTAL (3 * GSTAGE * 2)  // bytes = 122880

template <int EPI>
__global__ void __launch_bounds__(256)
hgemm_kernel(const __nv_bfloat16* __restrict__ Ah, const __nv_bfloat16* __restrict__ Al,
             const __nv_bfloat16* __restrict__ Wh, const __nv_bfloat16* __restrict__ Wl,
             const float* __restrict__ bias, float* __restrict__ C,
             int M, int N, int K)
{
    extern __shared__ __nv_bfloat16 gsm[];
    const uint32_t sb = smem_u32(gsm);

    const int tid = threadIdx.x;
    const int w = tid >> 5, lane = tid & 31;
    const int gid = lane >> 2, tig = lane & 3;
    const int wm = w & 3, wn = w >> 2;
    const int m0 = blockIdx.y * 128, n0 = blockIdx.x * 128;

    const int lrow = tid >> 1;
    const int lcol = (tid & 1) * 16;

    float acc[2][8][4];
#pragma unroll
    for (int mi = 0; mi < 2; mi++)
#pragma unroll
        for (int ni = 0; ni < 8; ni++)
            acc[mi][ni][0]=acc[mi][ni][1]=acc[mi][ni][2]=acc[mi][ni][3]=0.f;

    const __nv_bfloat16* srcA[4] = {
        Ah + (size_t)(m0 + lrow) * K + lcol,
        Al + (size_t)(m0 + lrow) * K + lcol,
        Wh + (size_t)(n0 + lrow) * K + lcol,
        Wl + (size_t)(n0 + lrow) * K + lcol };

    const int NIT = K / 32;
    auto issue = [&](int st, int k0) {
#pragma unroll
        for (int tI = 0; tI < 4; tI++) {
            uint32_t d = sb + (st * GSTAGE + tI * GTILE + lrow * GSTK + lcol) * 2;
            const __nv_bfloat16* s = srcA[tI] + k0;
            cpa16(d, s);
            cpa16(d + 16, s + 8);
        }
    };

    issue(0, 0);  CP_COMMIT();
    issue(1, 32); CP_COMMIT();

    for (int kt = 0; kt < NIT; kt++) {
        CP_WAIT1();
        __syncthreads();
        int ns = kt + 2;
        if (ns < NIT) issue(ns % 3, ns * 32);
        CP_COMMIT();

        const __nv_bfloat16* sAh = gsm + (kt % 3) * GSTAGE;
        const __nv_bfloat16* sAl = sAh + GTILE;
        const __nv_bfloat16* sWh = sAh + 2 * GTILE;
        const __nv_bfloat16* sWl = sAh + 3 * GTILE;

#pragma unroll
        for (int kk = 0; kk < 2; kk++) {
            const int qc = kk * 16 + tig * 2;
            uint32_t aH[2][4], aL[2][4];
#pragma unroll
            for (int mi = 0; mi < 2; mi++) {
                int r = wm * 32 + mi * 16 + gid;
                aH[mi][0] = *(const uint32_t*)&sAh[r*GSTK + qc];
                aH[mi][1] = *(const uint32_t*)&sAh[(r+8)*GSTK + qc];
                aH[mi][2] = *(const uint32_t*)&sAh[r*GSTK + qc + 8];
                aH[mi][3] = *(const uint32_t*)&sAh[(r+8)*GSTK + qc + 8];
                aL[mi][0] = *(const uint32_t*)&sAl[r*GSTK + qc];
                aL[mi][1] = *(const uint32_t*)&sAl[(r+8)*GSTK + qc];
                aL[mi][2] = *(const uint32_t*)&sAl[r*GSTK + qc + 8];
                aL[mi][3] = *(const uint32_t*)&sAl[(r+8)*GSTK + qc + 8];
            }
#pragma unroll
            for (int ni = 0; ni < 8; ni++) {
                int rn = wn * 64 + ni * 8 + gid;
                uint32_t bH[2], bL[2];
                bH[0] = *(const uint32_t*)&sWh[rn*GSTK + qc];
                bH[1] = *(const uint32_t*)&sWh[rn*GSTK + qc + 8];
                bL[0] = *(const uint32_t*)&sWl[rn*GSTK + qc];
                bL[1] = *(const uint32_t*)&sWl[rn*GSTK + qc + 8];
#pragma unroll
                for (int mi = 0; mi < 2; mi++) {
                    mma16816(acc[mi][ni], aH[mi], bH);
                    mma16816(acc[mi][ni], aH[mi], bL);
                    mma16816(acc[mi][ni], aL[mi], bH);
                }
            }
        }
    }

    // epilogue
#pragma unroll
    for (int mi = 0; mi < 2; mi++) {
#pragma unroll
        for (int rr = 0; rr < 2; rr++) {
            int m = m0 + wm * 32 + mi * 16 + gid + rr * 8;
#pragma unroll
            for (int ni = 0; ni < 8; ni++) {
                int n = n0 + wn * 64 + ni * 8 + tig * 2;
                float v0 = acc[mi][ni][rr*2+0] + bias[n];
                float v1 = acc[mi][ni][rr*2+1] + bias[n+1];
                if (EPI == 0) {
                    *(float2*)(C + (size_t)m * N + n) = make_float2(v0, v1);
                } else {
                    int h  = n / 192;
                    int r2 = n - h * 192;
                    int wch = r2 >> 6;
                    int hd = r2 & 63;
                    int bb = m >> 11, ss = m & (S_ - 1);
                    size_t di = ((size_t)(bb * H_ + h) * S_ + ss) * HD_ + hd;
                    __nv_bfloat16* dh = (wch == 0) ? g_qh : (wch == 1) ? g_kh : g_vh;
                    __nv_bfloat16* dl = (wch == 0) ? g_ql : (wch == 1) ? g_kl : g_vl;
                    __nv_bfloat16 h0,h1,l0,l1;
                    split1(v0,h0,l0); split1(v1,h1,l1);
                    *(uint32_t*)(dh + di) = pckh(h0,h1);
                    *(uint32_t*)(dl + di) = pckh(l0,l1);
                }
            }
        }
    }
}

// ---------------- attention smem layout (bf16 elems), stride 72 --------------
#define STK 72
#define AOFF_QH 0
#define AOFF_QL 9216
#define AOFF_K  18432            // 2 stages x (KH 4608 + KL 4608)
#define AKSTAGE 9216
#define AOFF_VTH 36864
#define AOFF_VTL 41472
#define ASM_ELEMS 46080          // 92160 bytes

// ================= attention: HMMA split-bf16, two-pass, cp.async ===========
__global__ void __launch_bounds__(256)
attn_mma_kernel(float* __restrict__ gAttn, int writeAttn)
{
    extern __shared__ __nv_bfloat16 sm[];
    const uint32_t sb = smem_u32(sm);
    __nv_bfloat16* Qhs = sm + AOFF_QH;
    __nv_bfloat16* Qls = sm + AOFF_QL;
    __nv_bfloat16* Vth = sm + AOFF_VTH;
    __nv_bfloat16* Vtl = sm + AOFF_VTL;

    const int tid = threadIdx.x;
    const int w = tid >> 5, lane = tid & 31;
    const int gid = lane >> 2, tig = lane & 3;
    const int qt = blockIdx.x, bh = blockIdx.y;
    const int sq = qt * 128;

    const size_t qoff = ((size_t)bh * S_ + sq) * HD_;
    const size_t koff = (size_t)bh * S_ * HD_;

    auto issueK = [&](int st, int t) {
        const __nv_bfloat16* kh = g_kh + koff + t * 4096;
        const __nv_bfloat16* kl = g_kl + koff + t * 4096;
        int base = AOFF_K + st * AKSTAGE;
#pragma unroll
        for (int it = 0; it < 2; it++) {
            int c = it * 256 + tid;          // 0..511
            int row = c >> 3, k8 = (c & 7) * 8;
            cpa16(sb + (base + row * STK + k8) * 2,        kh + row * 64 + k8);
            cpa16(sb + (base + 4608 + row * STK + k8) * 2, kl + row * 64 + k8);
        }
    };

    // ---- load Q tile (128x64) hi/lo ----------------------------------------
#pragma unroll
    for (int it = 0; it < 8; it++) {
        int f4 = it * 256 + tid;
        int r = f4 >> 4, c = (f4 & 15) << 2;
        *(uint2*)&Qhs[r*STK + c] = ((const uint2*)(g_qh + qoff))[f4];
        *(uint2*)&Qls[r*STK + c] = ((const uint2*)(g_ql + qoff))[f4];
    }

    const int qr = w * 16 + gid;
    float m0 = -1e30f, m1 = -1e30f, l0s = 0.f, l1s = 0.f;

    // helper macro body for S computation from stage st
    issueK(0, 0); CP_COMMIT();

    // =================== pass 1: rowmax m, denom l ===========================
    for (int t = 0; t < 32; t++) {
        CP_WAIT0();
        __syncthreads();
        if (t + 1 < 32) issueK((t + 1) & 1, t + 1);
        CP_COMMIT();

        const __nv_bfloat16* Khs = sm + AOFF_K + (t & 1) * AKSTAGE;
        const __nv_bfloat16* Kls = Khs + 4608;

        float s[8][4];
#pragma unroll
        for (int nc = 0; nc < 8; nc++)
            s[nc][0]=s[nc][1]=s[nc][2]=s[nc][3]=0.f;

#pragma unroll
        for (int kc = 0; kc < 4; kc++) {
            int qc = kc*16 + tig*2;
            uint32_t aH[4], aL[4];
            aH[0] = *(const uint32_t*)&Qhs[qr*STK + qc];
            aH[1] = *(const uint32_t*)&Qhs[(qr+8)*STK + qc];
            aH[2] = *(const uint32_t*)&Qhs[qr*STK + qc + 8];
            aH[3] = *(const uint32_t*)&Qhs[(qr+8)*STK + qc + 8];
            aL[0] = *(const uint32_t*)&Qls[qr*STK + qc];
            aL[1] = *(const uint32_t*)&Qls[(qr+8)*STK + qc];
            aL[2] = *(const uint32_t*)&Qls[qr*STK + qc + 8];
            aL[3] = *(const uint32_t*)&Qls[(qr+8)*STK + qc + 8];
#pragma unroll
            for (int nc = 0; nc < 8; nc++) {
                int kr = nc*8 + gid;
                uint32_t bH[2], bL[2];
                bH[0] = *(const uint32_t*)&Khs[kr*STK + qc];
                bH[1] = *(const uint32_t*)&Khs[kr*STK + qc + 8];
                bL[0] = *(const uint32_t*)&Kls[kr*STK + qc];
                bL[1] = *(const uint32_t*)&Kls[kr*STK + qc + 8];
                mma16816(s[nc], aH, bH);
                mma16816(s[nc], aH, bL);
                mma16816(s[nc], aL, bH);
            }
        }

        float mx0 = -1e30f, mx1 = -1e30f;
#pragma unroll
        for (int nc = 0; nc < 8; nc++) {
            s[nc][0]*=0.125f; s[nc][1]*=0.125f; s[nc][2]*=0.125f; s[nc][3]*=0.125f;
            mx0 = fmaxf(mx0, fmaxf(s[nc][0], s[nc][1]));
            mx1 = fmaxf(mx1, fmaxf(s[nc][2], s[nc][3]));
        }
        mx0 = fmaxf(mx0, __shfl_xor_sync(0xffffffffu, mx0, 1));
        mx0 = fmaxf(mx0, __shfl_xor_sync(0xffffffffu, mx0, 2));
        mx1 = fmaxf(mx1, __shfl_xor_sync(0xffffffffu, mx1, 1));
        mx1 = fmaxf(mx1, __shfl_xor_sync(0xffffffffu, mx1, 2));
        float mn0 = fmaxf(m0, mx0), mn1 = fmaxf(m1, mx1);
        float ps0 = 0.f, ps1 = 0.f;
#pragma unroll
        for (int nc = 0; nc < 8; nc++) {
            ps0 += fexp(s[nc][0]-mn0) + fexp(s[nc][1]-mn0);
            ps1 += fexp(s[nc][2]-mn1) + fexp(s[nc][3]-mn1);
        }
        ps0 += __shfl_xor_sync(0xffffffffu, ps0, 1);
        ps0 += __shfl_xor_sync(0xffffffffu, ps0, 2);
        ps1 += __shfl_xor_sync(0xffffffffu, ps1, 1);
        ps1 += __shfl_xor_sync(0xffffffffu, ps1, 2);
        l0s = l0s * fexp(m0 - mn0) + ps0;  m0 = mn0;
        l1s = l1s * fexp(m1 - mn1) + ps1;  m1 = mn1;
    }
    const float invl0 = 1.0f / l0s;
    const float invl1 = 1.0f / l1s;

    float o[8][4];
#pragma unroll
    for (int nd = 0; nd < 8; nd++)
        o[nd][0]=o[nd][1]=o[nd][2]=o[nd][3]=0.f;

    issueK(0, 0); CP_COMMIT();

    // =================== pass 2: normalized P out + O = P@V ==================
    for (int t = 0; t < 32; t++) {
        CP_WAIT0();
        __syncthreads();
        if (t + 1 < 32) issueK((t + 1) & 1, t + 1);
        CP_COMMIT();

        // V tile -> registers early (latency hidden by S MMA)
        uint2 vhr[4], vlr[4];
#pragma unroll
        for (int it = 0; it < 4; it++) {
            int f4 = it * 256 + tid;
            vhr[it] = ((const uint2*)(g_vh + koff + t*4096))[f4];
            vlr[it] = ((const uint2*)(g_vl + koff + t*4096))[f4];
        }

        const __nv_bfloat16* Khs = sm + AOFF_K + (t & 1) * AKSTAGE;
        const __nv_bfloat16* Kls = Khs + 4608;

        float s[8][4];
#pragma unroll
        for (int nc = 0; nc < 8; nc++)
            s[nc][0]=s[nc][1]=s[nc][2]=s[nc][3]=0.f;

#pragma unroll
        for (int kc = 0; kc < 4; kc++) {
            int qc = kc*16 + tig*2;
            uint32_t aH[4], aL[4];
            aH[0] = *(const uint32_t*)&Qhs[qr*STK + qc];
            aH[1] = *(const uint32_t*)&Qhs[(qr+8)*STK + qc];
            aH[2] = *(const uint32_t*)&Qhs[qr*STK + qc + 8];
            aH[3] = *(const uint32_t*)&Qhs[(qr+8)*STK + qc + 8];
            aL[0] = *(const uint32_t*)&Qls[qr*STK + qc];
            aL[1] = *(const uint32_t*)&Qls[(qr+8)*STK + qc];
            aL[2] = *(const uint32_t*)&Qls[qr*STK + qc + 8];
            aL[3] = *(const uint32_t*)&Qls[(qr+8)*STK + qc + 8];
#pragma unroll
            for (int nc = 0; nc < 8; nc++) {
                int kr = nc*8 + gid;
                uint32_t bH[2], bL[2];
                bH[0] = *(const uint32_t*)&Khs[kr*STK + qc];
                bH[1] = *(const uint32_t*)&Khs[kr*STK + qc + 8];
                bL[0] = *(const uint32_t*)&Kls[kr*STK + qc];
                bL[1] = *(const uint32_t*)&Kls[kr*STK + qc + 8];
                mma16816(s[nc], aH, bH);
                mma16816(s[nc], aH, bL);
                mma16816(s[nc], aL, bH);
            }
        }

        // V^T stores into (now-free) Vt buffer
#pragma unroll
        for (int it = 0; it < 4; it++) {
            int f4 = it * 256 + tid;
            int r = f4 >> 4, c = (f4 & 15) << 2;
            const __nv_bfloat16* ph = (const __nv_bfloat16*)&vhr[it];
            const __nv_bfloat16* pl = (const __nv_bfloat16*)&vlr[it];
#pragma unroll
            for (int j = 0; j < 4; j++) {
                Vth[(c+j)*STK + r] = ph[j];
                Vtl[(c+j)*STK + r] = pl[j];
            }
        }

#pragma unroll
        for (int nc = 0; nc < 8; nc++) {
            s[nc][0] = fexp(s[nc][0]*0.125f - m0) * invl0;
            s[nc][1] = fexp(s[nc][1]*0.125f - m0) * invl0;
            s[nc][2] = fexp(s[nc][2]*0.125f - m1) * invl1;
            s[nc][3] = fexp(s[nc][3]*0.125f - m1) * invl1;
        }

        if (writeAttn) {
            float* gA = gAttn + ((size_t)bh * S_ + sq + qr) * S_ + t*64 + tig*2;
#pragma unroll
            for (int nc = 0; nc < 8; nc++) {
                *(float2*)(gA + nc*8)        = make_float2(s[nc][0], s[nc][1]);
                *(float2*)(gA + 8*S_ + nc*8) = make_float2(s[nc][2], s[nc][3]);
            }
        }

        __syncthreads();   // V^T visible to all warps before PV

        // PV: A-fragments directly from S accumulators
#pragma unroll
        for (int kc = 0; kc < 4; kc++) {
            uint32_t aH[4], aL[4];
            {
                const float* p0 = s[2*kc];
                const float* p1 = s[2*kc+1];
                __nv_bfloat16 h00,h01,h02,h03,h10,h11,h12,h13;
                __nv_bfloat16 q00,q01,q02,q03,q10,q11,q12,q13;
                split1(p0[0],h00,q00); split1(p0[1],h01,q01);
                split1(p0[2],h02,q02); split1(p0[3],h03,q03);
                split1(p1[0],h10,q10); split1(p1[1],h11,q11);
                split1(p1[2],h12,q12); split1(p1[3],h13,q13);
                aH[0]=pckh(h00,h01); aH[1]=pckh(h02,h03);
                aH[2]=pckh(h10,h11); aH[3]=pckh(h12,h13);
                aL[0]=pckh(q00,q01); aL[1]=pckh(q02,q03);
                aL[2]=pckh(q10,q11); aL[3]=pckh(q12,q13);
            }
            int vc = kc*16 + tig*2;
#pragma unroll
            for (int nd = 0; nd < 8; nd++) {
                int vr = nd*8 + gid;
                uint32_t bH[2], bL[2];
                bH[0] = *(const uint32_t*)&Vth[vr*STK + vc];
                bH[1] = *(const uint32_t*)&Vth[vr*STK + vc + 8];
                bL[0] = *(const uint32_t*)&Vtl[vr*STK + vc];
                bL[1] = *(const uint32_t*)&Vtl[vr*STK + vc + 8];
                mma16816(o[nd], aH, bH);
                mma16816(o[nd], aH, bL);
                mma16816(o[nd], aL, bH);
            }
        }
    }

    // O -> hi/lo bf16 in [B,H,S,hd] layout (== the buggy reshape) for out GEMM
    {
        size_t ob = ((size_t)bh * S_ + sq + qr) * HD_ + tig*2;
#pragma unroll
        for (int nd = 0; nd < 8; nd++) {
            __nv_bfloat16 h0,h1,h2,h3,l0,l1,l2,l3;
            split1(o[nd][0],h0,l0); split1(o[nd][1],h1,l1);
            split1(o[nd][2],h2,l2); split1(o[nd][3],h3,l3);
            *(uint32_t*)(g_vfh + ob + nd*8)          = pckh(h0,h1);
            *(uint32_t*)(g_vfl + ob + nd*8)          = pckh(l0,l1);
            *(uint32_t*)(g_vfh + ob + 8*HD_ + nd*8)  = pckh(h2,h3);
            *(uint32_t*)(g_vfl + ob + 8*HD_ + nd*8)  = pckh(l2,l3);
        }
    }
}

// ---------------------------------------------------------------------------
extern "C" void kernel_launch(void* const* d_in, const int* in_sizes, int n_in,
                              void* d_out, int out_size)
{
    const float* x     = (const float*)d_in[0];
    const float* w_qkv = (const float*)d_in[1];
    const float* b_qkv = (const float*)d_in[2];
    const float* w_out = (const float*)d_in[3];
    const float* b_out = (const float*)d_in[4];
    float* out = (float*)d_out;

    const long long BSD  = (long long)B_ * S_ * D_;
    const long long BHSS = (long long)B_ * H_ * S_ * S_;

    float* outp = nullptr;
    float* attnp = nullptr;
    int wA = 0;
    if ((long long)out_size >= BSD + BHSS) { outp = out; attnp = out + BSD; wA = 1; }
    else if ((long long)out_size == BHSS)  { attnp = out; wA = 1; }
    else                                   { outp = out; }

    cudaFuncSetAttribute(attn_mma_kernel, cudaFuncAttributeMaxDynamicSharedMemorySize,
                         ASM_ELEMS * (int)sizeof(__nv_bfloat16));
    cudaFuncSetAttribute(hgemm_kernel<0>, cudaFuncAttributeMaxDynamicSharedMemorySize,
                         GSM_TOTAL);
    cudaFuncSetAttribute(hgemm_kernel<1>, cudaFuncAttributeMaxDynamicSharedMemorySize,
                         GSM_TOTAL);

    __nv_bfloat16 *xh, *xl, *wqh, *wql, *woh, *wol, *vfh, *vfl;
    cudaGetSymbolAddress((void**)&xh,  g_xh);  cudaGetSymbolAddress((void**)&xl,  g_xl);
    cudaGetSymbolAddress((void**)&wqh, g_wqh); cudaGetSymbolAddress((void**)&wql, g_wql);
    cudaGetSymbolAddress((void**)&woh, g_woh); cudaGetSymbolAddress((void**)&wol, g_wol);
    cudaGetSymbolAddress((void**)&vfh, g_vfh); cudaGetSymbolAddress((void**)&vfl, g_vfl);

    // K0: pre-split fp32 -> hi/lo bf16
    {
        int n4x = (B_ * S_ * D_) / 4, n4q = (TD_ * D_) / 4, n4o = (D_ * D_) / 4;
        split_kernel<<<(n4x + 255) / 256, 256>>>(x,     xh,  xl,  n4x);
        split_kernel<<<(n4q + 255) / 256, 256>>>(w_qkv, wqh, wql, n4q);
        split_kernel<<<(n4o + 255) / 256, 256>>>(w_out, woh, wol, n4o);
    }
    // K1: fused QKV projection (HMMA, pipelined)
    {
        dim3 grid(TD_ / 128, (B_ * S_) / 128);
        hgemm_kernel<1><<<grid, 256, GSM_TOTAL>>>(xh, xl, wqh, wql, b_qkv, nullptr,
                                                  B_ * S_, TD_, D_);
    }
    // K2: HMMA attention (pipelined)
    {
        dim3 grid(S_ / 128, B_ * H_);
        attn_mma_kernel<<<grid, 256, ASM_ELEMS * (int)sizeof(__nv_bfloat16)>>>(attnp, wA);
    }
    // K3: output projection (HMMA, pipelined)
    if (outp) {
        dim3 grid(D_ / 128, (B_ * S_) / 128);
        hgemm_kernel<0><<<grid, 256, GSM_TOTAL>>>(vfh, vfl, woh, wol, b_out, outp,
                                                  B_ * S_, D_, D_);
    }
}

// round 11
// speedup vs baseline: 2.6078x; 1.1776x over previous
#include <cuda_runtime.h>
#include <cuda_bf16.h>
#include <cstdint>

#define B_  4
#define S_  2048
#define D_  1024
#define H_  16
#define HD_ 64
#define TD_ 3072   // 3*D
#define NQKV (B_ * H_ * S_ * HD_)   // 8,388,608

// ---------------- scratch: hi/lo bf16 split tensors --------------------------
__device__ __nv_bfloat16 g_xh[B_ * S_ * D_],  g_xl[B_ * S_ * D_];
__device__ __nv_bfloat16 g_wqh[TD_ * D_],     g_wql[TD_ * D_];
__device__ __nv_bfloat16 g_woh[D_ * D_],      g_wol[D_ * D_];
__device__ __nv_bfloat16 g_qh[NQKV], g_ql[NQKV];
__device__ __nv_bfloat16 g_kh[NQKV], g_kl[NQKV];
__device__ __nv_bfloat16 g_vh[NQKV], g_vl[NQKV];
__device__ __nv_bfloat16 g_vfh[B_ * S_ * D_], g_vfl[B_ * S_ * D_];

// ---------------- fast exp (5-FMA poly) --------------------------------------
__device__ __forceinline__ float fexp(float x) {
    x = fmaxf(x, -80.0f);
    float y = x * 1.44269504088896340736f;
    float t = y + 12582912.0f;
    int   i = __float_as_int(t) - 0x4b400000;
    float f = y - (t - 12582912.0f);
    float p =              1.33336500e-3f;
    p = fmaf(p, f,         9.61793571e-3f);
    p = fmaf(p, f,         5.55041086e-2f);
    p = fmaf(p, f,         2.40226507e-1f);
    p = fmaf(p, f,         6.93147181e-1f);
    p = fmaf(p, f,         1.0f);
    return __int_as_float(__float_as_int(p) + (i << 23));
}

// ---------------- helpers ----------------------------------------------------
__device__ __forceinline__ void split1(float x, __nv_bfloat16& h, __nv_bfloat16& l) {
    h = __float2bfloat16_rn(x);
    l = __float2bfloat16_rn(x - __bfloat162float(h));
}
__device__ __forceinline__ uint32_t pckh(__nv_bfloat16 a, __nv_bfloat16 b) {
    __nv_bfloat162 t = __halves2bfloat162(a, b);
    return *reinterpret_cast<uint32_t*>(&t);
}
__device__ __forceinline__ void mma16816(float c[4], const uint32_t a[4], const uint32_t b[2]) {
    asm volatile(
        "mma.sync.aligned.m16n8k16.row.col.f32.bf16.bf16.f32 "
        "{%0,%1,%2,%3}, {%4,%5,%6,%7}, {%8,%9}, {%0,%1,%2,%3};"
        : "+f"(c[0]), "+f"(c[1]), "+f"(c[2]), "+f"(c[3])
        : "r"(a[0]), "r"(a[1]), "r"(a[2]), "r"(a[3]), "r"(b[0]), "r"(b[1]));
}
__device__ __forceinline__ uint32_t smem_u32(const void* p) {
    uint32_t a;
    asm("{ .reg .u64 t; cvta.to.shared.u64 t, %1; cvt.u32.u64 %0, t; }" : "=r"(a) : "l"(p));
    return a;
}
__device__ __forceinline__ void cpa16(uint32_t d, const void* s) {
    asm volatile("cp.async.cg.shared.global [%0], [%1], 16;" :: "r"(d), "l"(s));
}
#define CP_COMMIT() asm volatile("cp.async.commit_group;" ::: "memory")
#define CP_WAIT0()  asm volatile("cp.async.wait_group 0;" ::: "memory")
#define CP_WAIT1()  asm volatile("cp.async.wait_group 1;" ::: "memory")

__device__ __forceinline__ void ldsm4(uint32_t* r, uint32_t a) {
    asm volatile("ldmatrix.sync.aligned.m8n8.x4.shared.b16 {%0,%1,%2,%3}, [%4];"
        : "=r"(r[0]), "=r"(r[1]), "=r"(r[2]), "=r"(r[3]) : "r"(a));
}
__device__ __forceinline__ void ldsm4t(uint32_t* r, uint32_t a) {
    asm volatile("ldmatrix.sync.aligned.m8n8.x4.trans.shared.b16 {%0,%1,%2,%3}, [%4];"
        : "=r"(r[0]), "=r"(r[1]), "=r"(r[2]), "=r"(r[3]) : "r"(a));
}

// ================= pre-split: fp32 -> (hi, lo) bf16 ==========================
__global__ void split_kernel(const float* __restrict__ src,
                             __nv_bfloat16* __restrict__ dh,
                             __nv_bfloat16* __restrict__ dl, int n4)
{
    int i = blockIdx.x * blockDim.x + threadIdx.x;
    if (i >= n4) return;
    float4 v = ((const float4*)src)[i];
    __nv_bfloat16 h0,h1,h2,h3,l0,l1,l2,l3;
    split1(v.x,h0,l0); split1(v.y,h1,l1); split1(v.z,h2,l2); split1(v.w,h3,l3);
    ((uint2*)dh)[i] = make_uint2(pckh(h0,h1), pckh(h2,h3));
    ((uint2*)dl)[i] = make_uint2(pckh(l0,l1), pckh(l2,l3));
}

// ================= HMMA split-bf16 GEMM, 3-stage cp.async + ldmatrix ========
#define GSTK 40
#define GTILE (128 * GSTK)
#define GSTAGE (4 * GTILE)
#define GSM_TOTAL (3 * GSTAGE * 2)   // 122880 bytes

template <int EPI>
__global__ void __launch_bounds__(256)
hgemm_kernel(const __nv_bfloat16* __restrict__ Ah, const __nv_bfloat16* __restrict__ Al,
             const __nv_bfloat16* __restrict__ Wh, const __nv_bfloat16* __restrict__ Wl,
             const float* __restrict__ bias, float* __restrict__ C,
             int M, int N, int K)
{
    extern __shared__ __nv_bfloat16 gsm[];
    const uint32_t sb = smem_u32(gsm);

    const int tid = threadIdx.x;
    const int w = tid >> 5, lane = tid & 31;
    const int gid = lane >> 2, tig = lane & 3;
    const int wm = w & 3, wn = w >> 2;
    const int m0 = blockIdx.y * 128, n0 = blockIdx.x * 128;

    const int lrow = tid >> 1;
    const int lcol = (tid & 1) * 16;

    // per-lane ldmatrix offsets (bytes)
    const uint32_t aoffG = (uint32_t)(((lane & 15) * GSTK + ((lane >> 4) << 3)) * 2);
    const uint32_t boffG = (uint32_t)(((((lane >> 4) << 3) + (lane & 7)) * GSTK
                                      + (((lane >> 3) & 1) << 3)) * 2);

    float acc[2][8][4];
#pragma unroll
    for (int mi = 0; mi < 2; mi++)
#pragma unroll
        for (int ni = 0; ni < 8; ni++)
            acc[mi][ni][0]=acc[mi][ni][1]=acc[mi][ni][2]=acc[mi][ni][3]=0.f;

    const __nv_bfloat16* srcA[4] = {
        Ah + (size_t)(m0 + lrow) * K + lcol,
        Al + (size_t)(m0 + lrow) * K + lcol,
        Wh + (size_t)(n0 + lrow) * K + lcol,
        Wl + (size_t)(n0 + lrow) * K + lcol };

    const int NIT = K / 32;
    auto issue = [&](int st, int k0) {
#pragma unroll
        for (int tI = 0; tI < 4; tI++) {
            uint32_t d = sb + (st * GSTAGE + tI * GTILE + lrow * GSTK + lcol) * 2;
            const __nv_bfloat16* s = srcA[tI] + k0;
            cpa16(d, s);
            cpa16(d + 16, s + 8);
        }
    };

    issue(0, 0);  CP_COMMIT();
    issue(1, 32); CP_COMMIT();

    for (int kt = 0; kt < NIT; kt++) {
        CP_WAIT1();
        __syncthreads();
        int ns = kt + 2;
        if (ns < NIT) issue(ns % 3, ns * 32);
        CP_COMMIT();

        const uint32_t stb = sb + (uint32_t)((kt % 3) * GSTAGE * 2);
        const uint32_t stAh = stb, stAl = stb + GTILE * 2;
        const uint32_t stWh = stb + 2 * GTILE * 2, stWl = stb + 3 * GTILE * 2;

#pragma unroll
        for (int kk = 0; kk < 2; kk++) {
            const int qc0 = kk * 16;
            uint32_t aH[2][4], aL[2][4];
#pragma unroll
            for (int mi = 0; mi < 2; mi++) {
                uint32_t ro = (uint32_t)(((wm * 32 + mi * 16) * GSTK + qc0) * 2);
                ldsm4(aH[mi], stAh + ro + aoffG);
                ldsm4(aL[mi], stAl + ro + aoffG);
            }
#pragma unroll
            for (int nj = 0; nj < 4; nj++) {
                uint32_t bh4[4], bl4[4];
                uint32_t no = (uint32_t)(((wn * 64 + nj * 16) * GSTK + qc0) * 2);
                ldsm4(bh4, stWh + no + boffG);
                ldsm4(bl4, stWl + no + boffG);
#pragma unroll
                for (int mi = 0; mi < 2; mi++) {
                    mma16816(acc[mi][2*nj],   aH[mi], bh4);
                    mma16816(acc[mi][2*nj],   aH[mi], bl4);
                    mma16816(acc[mi][2*nj],   aL[mi], bh4);
                    mma16816(acc[mi][2*nj+1], aH[mi], bh4 + 2);
                    mma16816(acc[mi][2*nj+1], aH[mi], bl4 + 2);
                    mma16816(acc[mi][2*nj+1], aL[mi], bh4 + 2);
                }
            }
        }
    }

    // epilogue
#pragma unroll
    for (int mi = 0; mi < 2; mi++) {
#pragma unroll
        for (int rr = 0; rr < 2; rr++) {
            int m = m0 + wm * 32 + mi * 16 + gid + rr * 8;
#pragma unroll
            for (int ni = 0; ni < 8; ni++) {
                int n = n0 + wn * 64 + ni * 8 + tig * 2;
                float v0 = acc[mi][ni][rr*2+0] + bias[n];
                float v1 = acc[mi][ni][rr*2+1] + bias[n+1];
                if (EPI == 0) {
                    *(float2*)(C + (size_t)m * N + n) = make_float2(v0, v1);
                } else {
                    int h  = n / 192;
                    int r2 = n - h * 192;
                    int wch = r2 >> 6;
                    int hd = r2 & 63;
                    int bb = m >> 11, ss = m & (S_ - 1);
                    size_t di = ((size_t)(bb * H_ + h) * S_ + ss) * HD_ + hd;
                    __nv_bfloat16* dh = (wch == 0) ? g_qh : (wch == 1) ? g_kh : g_vh;
                    __nv_bfloat16* dl = (wch == 0) ? g_ql : (wch == 1) ? g_kl : g_vl;
                    __nv_bfloat16 h0,h1,l0,l1;
                    split1(v0,h0,l0); split1(v1,h1,l1);
                    *(uint32_t*)(dh + di) = pckh(h0,h1);
                    *(uint32_t*)(dl + di) = pckh(l0,l1);
                }
            }
        }
    }
}

// ---------------- attention smem (bf16 elems), stride 72 ---------------------
// QH 9216 | QL 9216 | K 2 stages x (KH 4608 + KL 4608) | V 2 stages x (...)
#define STK 72
#define ASM_ELEMS 55296          // 110592 bytes

// ================= attention: HMMA split-bf16 + ldmatrix, two-pass ==========
__global__ void __launch_bounds__(256)
attn_mma_kernel(float* __restrict__ gAttn, int writeAttn)
{
    extern __shared__ __nv_bfloat16 sm[];
    const uint32_t sb = smem_u32(sm);
    const uint32_t sbQH = sb, sbQL = sb + 18432;
    const uint32_t sbK  = sb + 36864;          // + st*18432 ; KL at +9216
    const uint32_t sbV  = sb + 73728;          // + st*18432 ; VL at +9216

    const int tid = threadIdx.x;
    const int w = tid >> 5, lane = tid & 31;
    const int gid = lane >> 2, tig = lane & 3;
    const int qt = blockIdx.x, bh = blockIdx.y;
    const int sq = qt * 128;

    const size_t qoff = ((size_t)bh * S_ + sq) * HD_;
    const size_t koff = (size_t)bh * S_ * HD_;

    // per-lane ldmatrix offsets (bytes)
    const uint32_t aoff = (uint32_t)(((lane & 15) * STK + ((lane >> 4) << 3)) * 2);
    const uint32_t boff = (uint32_t)(((((lane >> 4) << 3) + (lane & 7)) * STK
                                     + (((lane >> 3) & 1) << 3)) * 2);
    const uint32_t voff = (uint32_t)((((((lane >> 3) & 1) << 3) + (lane & 7)) * STK
                                     + ((lane >> 4) << 3)) * 2);

    auto issueK = [&](int st, int t) {
        const __nv_bfloat16* kh = g_kh + koff + t * 4096;
        const __nv_bfloat16* kl = g_kl + koff + t * 4096;
        uint32_t base = sbK + st * 18432;
#pragma unroll
        for (int it = 0; it < 2; it++) {
            int c = it * 256 + tid;
            int row = c >> 3, k8 = (c & 7) * 8;
            uint32_t d = base + (uint32_t)((row * STK + k8) * 2);
            cpa16(d,        kh + row * 64 + k8);
            cpa16(d + 9216, kl + row * 64 + k8);
        }
    };
    auto issueV = [&](int st, int t) {
        const __nv_bfloat16* vh = g_vh + koff + t * 4096;
        const __nv_bfloat16* vl = g_vl + koff + t * 4096;
        uint32_t base = sbV + st * 18432;
#pragma unroll
        for (int it = 0; it < 2; it++) {
            int c = it * 256 + tid;
            int row = c >> 3, k8 = (c & 7) * 8;
            uint32_t d = base + (uint32_t)((row * STK + k8) * 2);
            cpa16(d,        vh + row * 64 + k8);
            cpa16(d + 9216, vl + row * 64 + k8);
        }
    };

    // ---- load Q tile (128x64) hi/lo to smem --------------------------------
    {
        __nv_bfloat16* Qhs = sm;
        __nv_bfloat16* Qls = sm + 9216;
#pragma unroll
        for (int it = 0; it < 8; it++) {
            int f4 = it * 256 + tid;
            int r = f4 >> 4, c = (f4 & 15) << 2;
            *(uint2*)&Qhs[r*STK + c] = ((const uint2*)(g_qh + qoff))[f4];
            *(uint2*)&Qls[r*STK + c] = ((const uint2*)(g_ql + qoff))[f4];
        }
    }
    issueK(0, 0); CP_COMMIT();
    __syncthreads();

    // ---- hoist Q fragments (loop-invariant) --------------------------------
    uint32_t qfh[4][4], qfl[4][4];
#pragma unroll
    for (int kc = 0; kc < 4; kc++) {
        uint32_t ro = (uint32_t)(((w * 16) * STK + kc * 16) * 2);
        ldsm4(qfh[kc], sbQH + ro + aoff);
        ldsm4(qfl[kc], sbQL + ro + aoff);
    }

    const int qr = w * 16 + gid;
    float m0 = -1e30f, m1 = -1e30f, l0s = 0.f, l1s = 0.f;

    // =================== pass 1: rowmax m, denom l ===========================
    for (int t = 0; t < 32; t++) {
        CP_WAIT0();
        __syncthreads();
        if (t + 1 < 32) issueK((t + 1) & 1, t + 1);
        CP_COMMIT();

        const uint32_t stKh = sbK + (t & 1) * 18432;
        const uint32_t stKl = stKh + 9216;

        float s[8][4];
#pragma unroll
        for (int nc = 0; nc < 8; nc++)
            s[nc][0]=s[nc][1]=s[nc][2]=s[nc][3]=0.f;

#pragma unroll
        for (int kc = 0; kc < 4; kc++) {
            const uint32_t co = (uint32_t)(kc * 16 * 2);
#pragma unroll
            for (int nj = 0; nj < 4; nj++) {
                uint32_t bh4[4], bl4[4];
                uint32_t no = (uint32_t)((nj * 16 * STK) * 2) + co;
                ldsm4(bh4, stKh + no + boff);
                ldsm4(bl4, stKl + no + boff);
                mma16816(s[2*nj],   qfh[kc], bh4);
                mma16816(s[2*nj],   qfh[kc], bl4);
                mma16816(s[2*nj],   qfl[kc], bh4);
                mma16816(s[2*nj+1], qfh[kc], bh4 + 2);
                mma16816(s[2*nj+1], qfh[kc], bl4 + 2);
                mma16816(s[2*nj+1], qfl[kc], bh4 + 2);
            }
        }

        float mx0 = -1e30f, mx1 = -1e30f;
#pragma unroll
        for (int nc = 0; nc < 8; nc++) {
            s[nc][0]*=0.125f; s[nc][1]*=0.125f; s[nc][2]*=0.125f; s[nc][3]*=0.125f;
            mx0 = fmaxf(mx0, fmaxf(s[nc][0], s[nc][1]));
            mx1 = fmaxf(mx1, fmaxf(s[nc][2], s[nc][3]));
        }
        mx0 = fmaxf(mx0, __shfl_xor_sync(0xffffffffu, mx0, 1));
        mx0 = fmaxf(mx0, __shfl_xor_sync(0xffffffffu, mx0, 2));
        mx1 = fmaxf(mx1, __shfl_xor_sync(0xffffffffu, mx1, 1));
        mx1 = fmaxf(mx1, __shfl_xor_sync(0xffffffffu, mx1, 2));
        float mn0 = fmaxf(m0, mx0), mn1 = fmaxf(m1, mx1);
        float ps0 = 0.f, ps1 = 0.f;
#pragma unroll
        for (int nc = 0; nc < 8; nc++) {
            ps0 += fexp(s[nc][0]-mn0) + fexp(s[nc][1]-mn0);
            ps1 += fexp(s[nc][2]-mn1) + fexp(s[nc][3]-mn1);
        }
        ps0 += __shfl_xor_sync(0xffffffffu, ps0, 1);
        ps0 += __shfl_xor_sync(0xffffffffu, ps0, 2);
        ps1 += __shfl_xor_sync(0xffffffffu, ps1, 1);
        ps1 += __shfl_xor_sync(0xffffffffu, ps1, 2);
        l0s = l0s * fexp(m0 - mn0) + ps0;  m0 = mn0;
        l1s = l1s * fexp(m1 - mn1) + ps1;  m1 = mn1;
    }
    const float invl0 = 1.0f / l0s;
    const float invl1 = 1.0f / l1s;

    float o[8][4];
#pragma unroll
    for (int nd = 0; nd < 8; nd++)
        o[nd][0]=o[nd][1]=o[nd][2]=o[nd][3]=0.f;

    issueK(0, 0); issueV(0, 0); CP_COMMIT();

    // =================== pass 2: normalized P out + O = P@V ==================
    for (int t = 0; t < 32; t++) {
        CP_WAIT0();
        __syncthreads();
        if (t + 1 < 32) { issueK((t + 1) & 1, t + 1); issueV((t + 1) & 1, t + 1); }
        CP_COMMIT();

        const uint32_t stKh = sbK + (t & 1) * 18432;
        const uint32_t stKl = stKh + 9216;
        const uint32_t stVh = sbV + (t & 1) * 18432;
        const uint32_t stVl = stVh + 9216;

        float s[8][4];
#pragma unroll
        for (int nc = 0; nc < 8; nc++)
            s[nc][0]=s[nc][1]=s[nc][2]=s[nc][3]=0.f;

#pragma unroll
        for (int kc = 0; kc < 4; kc++) {
            const uint32_t co = (uint32_t)(kc * 16 * 2);
#pragma unroll
            for (int nj = 0; nj < 4; nj++) {
                uint32_t bh4[4], bl4[4];
                uint32_t no = (uint32_t)((nj * 16 * STK) * 2) + co;
                ldsm4(bh4, stKh + no + boff);
                ldsm4(bl4, stKl + no + boff);
                mma16816(s[2*nj],   qfh[kc], bh4);
                mma16816(s[2*nj],   qfh[kc], bl4);
                mma16816(s[2*nj],   qfl[kc], bh4);
                mma16816(s[2*nj+1], qfh[kc], bh4 + 2);
                mma16816(s[2*nj+1], qfh[kc], bl4 + 2);
                mma16816(s[2*nj+1], qfl[kc], bh4 + 2);
            }
        }

#pragma unroll
        for (int nc = 0; nc < 8; nc++) {
            s[nc][0] = fexp(s[nc][0]*0.125f - m0) * invl0;
            s[nc][1] = fexp(s[nc][1]*0.125f - m0) * invl0;
            s[nc][2] = fexp(s[nc][2]*0.125f - m1) * invl1;
            s[nc][3] = fexp(s[nc][3]*0.125f - m1) * invl1;
        }

        if (writeAttn) {
            float* gA = gAttn + ((size_t)bh * S_ + sq + qr) * S_ + t*64 + tig*2;
#pragma unroll
            for (int nc = 0; nc < 8; nc++) {
                *(float2*)(gA + nc*8)        = make_float2(s[nc][0], s[nc][1]);
                *(float2*)(gA + 8*S_ + nc*8) = make_float2(s[nc][2], s[nc][3]);
            }
        }

        // PV: A-frags from S accumulators; B-frags via ldmatrix.trans on V
#pragma unroll
        for (int kc = 0; kc < 4; kc++) {
            uint32_t aH[4], aL[4];
            {
                const float* p0 = s[2*kc];
                const float* p1 = s[2*kc+1];
                __nv_bfloat16 h00,h01,h02,h03,h10,h11,h12,h13;
                __nv_bfloat16 q00,q01,q02,q03,q10,q11,q12,q13;
                split1(p0[0],h00,q00); split1(p0[1],h01,q01);
                split1(p0[2],h02,q02); split1(p0[3],h03,q03);
                split1(p1[0],h10,q10); split1(p1[1],h11,q11);
                split1(p1[2],h12,q12); split1(p1[3],h13,q13);
                aH[0]=pckh(h00,h01); aH[1]=pckh(h02,h03);
                aH[2]=pckh(h10,h11); aH[3]=pckh(h12,h13);
                aL[0]=pckh(q00,q01); aL[1]=pckh(q02,q03);
                aL[2]=pckh(q10,q11); aL[3]=pckh(q12,q13);
            }
            const uint32_t ko = (uint32_t)((kc * 16 * STK) * 2);
#pragma unroll
            for (int nj = 0; nj < 4; nj++) {
                uint32_t vh4[4], vl4[4];
                uint32_t no = ko + (uint32_t)(nj * 16 * 2);
                ldsm4t(vh4, stVh + no + voff);
                ldsm4t(vl4, stVl + no + voff);
                mma16816(o[2*nj],   aH, vh4);
                mma16816(o[2*nj],   aH, vl4);
                mma16816(o[2*nj],   aL, vh4);
                mma16816(o[2*nj+1], aH, vh4 + 2);
                mma16816(o[2*nj+1], aH, vl4 + 2);
                mma16816(o[2*nj+1], aL, vh4 + 2);
            }
        }
    }

    // O -> hi/lo bf16 in [B,H,S,hd] layout (== the buggy reshape) for out GEMM
    {
        size_t ob = ((size_t)bh * S_ + sq + qr) * HD_ + tig*2;
#pragma unroll
        for (int nd = 0; nd < 8; nd++) {
            __nv_bfloat16 h0,h1,h2,h3,l0,l1,l2,l3;
            split1(o[nd][0],h0,l0); split1(o[nd][1],h1,l1);
            split1(o[nd][2],h2,l2); split1(o[nd][3],h3,l3);
            *(uint32_t*)(g_vfh + ob + nd*8)          = pckh(h0,h1);
            *(uint32_t*)(g_vfl + ob + nd*8)          = pckh(l0,l1);
            *(uint32_t*)(g_vfh + ob + 8*HD_ + nd*8)  = pckh(h2,h3);
            *(uint32_t*)(g_vfl + ob + 8*HD_ + nd*8)  = pckh(l2,l3);
        }
    }
}

// ---------------------------------------------------------------------------
extern "C" void kernel_launch(void* const* d_in, const int* in_sizes, int n_in,
                              void* d_out, int out_size)
{
    const float* x     = (const float*)d_in[0];
    const float* w_qkv = (const float*)d_in[1];
    const float* b_qkv = (const float*)d_in[2];
    const float* w_out = (const float*)d_in[3];
    const float* b_out = (const float*)d_in[4];
    float* out = (float*)d_out;

    const long long BSD  = (long long)B_ * S_ * D_;
    const long long BHSS = (long long)B_ * H_ * S_ * S_;

    float* outp = nullptr;
    float* attnp = nullptr;
    int wA = 0;
    if ((long long)out_size >= BSD + BHSS) { outp = out; attnp = out + BSD; wA = 1; }
    else if ((long long)out_size == BHSS)  { attnp = out; wA = 1; }
    else                                   { outp = out; }

    cudaFuncSetAttribute(attn_mma_kernel, cudaFuncAttributeMaxDynamicSharedMemorySize,
                         ASM_ELEMS * (int)sizeof(__nv_bfloat16));
    cudaFuncSetAttribute(hgemm_kernel<0>, cudaFuncAttributeMaxDynamicSharedMemorySize,
                         GSM_TOTAL);
    cudaFuncSetAttribute(hgemm_kernel<1>, cudaFuncAttributeMaxDynamicSharedMemorySize,
                         GSM_TOTAL);

    __nv_bfloat16 *xh, *xl, *wqh, *wql, *woh, *wol, *vfh, *vfl;
    cudaGetSymbolAddress((void**)&xh,  g_xh);  cudaGetSymbolAddress((void**)&xl,  g_xl);
    cudaGetSymbolAddress((void**)&wqh, g_wqh); cudaGetSymbolAddress((void**)&wql, g_wql);
    cudaGetSymbolAddress((void**)&woh, g_woh); cudaGetSymbolAddress((void**)&wol, g_wol);
    cudaGetSymbolAddress((void**)&vfh, g_vfh); cudaGetSymbolAddress((void**)&vfl, g_vfl);

    // K0: pre-split fp32 -> hi/lo bf16
    {
        int n4x = (B_ * S_ * D_) / 4, n4q = (TD_ * D_) / 4, n4o = (D_ * D_) / 4;
        split_kernel<<<(n4x + 255) / 256, 256>>>(x,     xh,  xl,  n4x);
        split_kernel<<<(n4q + 255) / 256, 256>>>(w_qkv, wqh, wql, n4q);
        split_kernel<<<(n4o + 255) / 256, 256>>>(w_out, woh, wol, n4o);
    }
    // K1: fused QKV projection (HMMA + ldmatrix)
    {
        dim3 grid(TD_ / 128, (B_ * S_) / 128);
        hgemm_kernel<1><<<grid, 256, GSM_TOTAL>>>(xh, xl, wqh, wql, b_qkv, nullptr,
                                                  B_ * S_, TD_, D_);
    }
    // K2: HMMA attention (ldmatrix + trans-V)
    {
        dim3 grid(S_ / 128, B_ * H_);
        attn_mma_kernel<<<grid, 256, ASM_ELEMS * (int)sizeof(__nv_bfloat16)>>>(attnp, wA);
    }
    // K3: output projection
    if (outp) {
        dim3 grid(D_ / 128, (B_ * S_) / 128);
        hgemm_kernel<0><<<grid, 256, GSM_TOTAL>>>(vfh, vfl, woh, wol, b_out, outp,
                                                  B_ * S_, D_, D_);
    }
}